// round 1
// baseline (speedup 1.0000x reference)
#include <cuda_runtime.h>
#include <cuda_bf16.h>
#include <cstdint>

// Problem constants
#define BB   128
#define TT   1024
#define II   256
#define HH   512
#define CC   32

// ---------------- f32x2 / SMEM asm helpers ----------------

__device__ __forceinline__ unsigned smem_u32(const void* p) {
    return (unsigned)__cvta_generic_to_shared(p);
}

__device__ __forceinline__ unsigned long long lds64v(unsigned a) {
    unsigned long long v;
    asm volatile("ld.shared.b64 %0, [%1];" : "=l"(v) : "r"(a));
    return v;
}

__device__ __forceinline__ float4 lds128v(unsigned a) {
    float4 v;
    asm volatile("ld.shared.v4.f32 {%0,%1,%2,%3}, [%4];"
                 : "=f"(v.x), "=f"(v.y), "=f"(v.z), "=f"(v.w) : "r"(a));
    return v;
}

__device__ __forceinline__ unsigned long long dup2(float x) {
    unsigned xi = __float_as_uint(x);
    unsigned long long v;
    asm("mov.b64 %0, {%1, %1};" : "=l"(v) : "r"(xi));
    return v;
}

__device__ __forceinline__ unsigned long long pack2(float x, float y) {
    unsigned xi = __float_as_uint(x), yi = __float_as_uint(y);
    unsigned long long v;
    asm("mov.b64 %0, {%1, %2};" : "=l"(v) : "r"(xi), "r"(yi));
    return v;
}

__device__ __forceinline__ float2 unpack2(unsigned long long v) {
    unsigned a, b;
    asm("mov.b64 {%0, %1}, %2;" : "=r"(a), "=r"(b) : "l"(v));
    return make_float2(__uint_as_float(a), __uint_as_float(b));
}

__device__ __forceinline__ void fma2(unsigned long long& acc,
                                     unsigned long long a,
                                     unsigned long long b) {
    asm("fma.rn.f32x2 %0, %1, %2, %0;" : "+l"(acc) : "l"(a), "l"(b));
}

__device__ __forceinline__ unsigned long long add2(unsigned long long a,
                                                   unsigned long long b) {
    unsigned long long d;
    asm("add.rn.f32x2 %0, %1, %2;" : "=l"(d) : "l"(a), "l"(b));
    return d;
}

__device__ __forceinline__ unsigned mapa_cluster(unsigned addr, unsigned rank) {
    unsigned r;
    asm("mapa.shared::cluster.u32 %0, %1, %2;" : "=r"(r) : "r"(addr), "r"(rank));
    return r;
}

__device__ __forceinline__ void st_cluster64(unsigned addr, unsigned long long v) {
    asm volatile("st.shared::cluster.b64 [%0], %1;" :: "r"(addr), "l"(v) : "memory");
}

__device__ __forceinline__ unsigned cluster_rank() {
    unsigned r;
    asm("mov.u32 %0, %%cluster_ctarank;" : "=r"(r));
    return r;
}

__device__ __forceinline__ void cluster_sync_() {
    asm volatile("barrier.cluster.arrive.aligned;" ::: "memory");
    asm volatile("barrier.cluster.wait.aligned;" ::: "memory");
}

// ---------------- Kernel A: xp = x @ W_ih^T + b_ih  -> out[(b*T+t)*H + h] --------
// M = B*T = 131072, N = H = 512, K = I = 256.
// 64x64 block tile, 16-deep K tiles, 256 threads, 4m x 4n per thread via FFMA2.

__global__ void __launch_bounds__(256)
xp_gemm_kernel(const float* __restrict__ x, const float* __restrict__ W,
               const float* __restrict__ bias, float* __restrict__ out)
{
    __shared__ float As[16][64];   // [k][m]
    __shared__ float Bs[16][64];   // [k][h]

    const int tid = threadIdx.x;
    const int m0 = blockIdx.x * 64;
    const int h0 = blockIdx.y * 64;
    const int tx = tid & 15;       // n group
    const int ty = tid >> 4;       // m group
    const int ml = tid >> 2;       // staging row 0..63
    const int kl = (tid & 3) * 4;  // staging k offset

    unsigned long long acc[4][2];
#pragma unroll
    for (int i = 0; i < 4; i++) { acc[i][0] = 0ull; acc[i][1] = 0ull; }

    const float* xg = x + (size_t)(m0 + ml) * II + kl;
    const float* wg = W + (size_t)(h0 + ml) * II + kl;
    const unsigned aAddr = smem_u32(&As[0][ty * 4]);
    const unsigned bAddr = smem_u32(&Bs[0][tx * 4]);

    for (int kt = 0; kt < II; kt += 16) {
        float4 xv = *(const float4*)(xg + kt);
        float4 wv = *(const float4*)(wg + kt);
        __syncthreads();
        As[kl + 0][ml] = xv.x; As[kl + 1][ml] = xv.y;
        As[kl + 2][ml] = xv.z; As[kl + 3][ml] = xv.w;
        Bs[kl + 0][ml] = wv.x; Bs[kl + 1][ml] = wv.y;
        Bs[kl + 2][ml] = wv.z; Bs[kl + 3][ml] = wv.w;
        __syncthreads();
#pragma unroll
        for (int k = 0; k < 16; k++) {
            float4 a4 = lds128v(aAddr + (unsigned)(k * 256));
            unsigned long long b01 = lds64v(bAddr + (unsigned)(k * 256));
            unsigned long long b23 = lds64v(bAddr + (unsigned)(k * 256 + 8));
            unsigned long long d;
            d = dup2(a4.x); fma2(acc[0][0], b01, d); fma2(acc[0][1], b23, d);
            d = dup2(a4.y); fma2(acc[1][0], b01, d); fma2(acc[1][1], b23, d);
            d = dup2(a4.z); fma2(acc[2][0], b01, d); fma2(acc[2][1], b23, d);
            d = dup2(a4.w); fma2(acc[3][0], b01, d); fma2(acc[3][1], b23, d);
        }
    }

    const float2 bias01 = *(const float2*)&bias[h0 + tx * 4];
    const float2 bias23 = *(const float2*)&bias[h0 + tx * 4 + 2];
#pragma unroll
    for (int i = 0; i < 4; i++) {
        float2 c01 = unpack2(acc[i][0]);
        float2 c23 = unpack2(acc[i][1]);
        float4 res;
        res.x = c01.x + bias01.x;
        res.y = c01.y + bias01.y;
        res.z = c23.x + bias23.x;
        res.w = c23.y + bias23.y;
        *(float4*)&out[(size_t)(m0 + ty * 4 + i) * HH + h0 + tx * 4] = res;
    }
}

// ---------------- Kernel B: cp[b][h] = constraints[b]@W_ch[h] + b_ch[h] + b_hh[h]

__device__ float g_cp[BB * HH];

__global__ void __launch_bounds__(512)
cp_kernel(const float* __restrict__ cons, const float* __restrict__ W_ch,
          const float* __restrict__ b_ch, const float* __restrict__ b_hh)
{
    __shared__ float cs[CC];
    const int b = blockIdx.x;
    const int h = threadIdx.x;
    if (h < CC) cs[h] = cons[b * CC + h];
    __syncthreads();
    float s = b_ch[h] + b_hh[h];
#pragma unroll
    for (int c = 0; c < CC; c++) s += cs[c] * W_ch[h * CC + c];
    g_cp[b * HH + h] = s;
}

// ---------------- Kernel C: sequential recurrence -----------------------------
// Cluster of 8 CTAs; CTA (rank r) holds W_hh rows [r*64, r*64+64) transposed in
// SMEM (Wt[k][jj], row stride 66). Each cluster handles 8 batch rows. Each step:
// every CTA computes its 8x64 slice h_new = tanh(xp + cp + h @ Wslice^T) from a
// local full-h copy, then broadcasts the slice to all 8 CTAs' h_next buffers via
// DSMEM; one cluster barrier per step; double-buffered h.
//
// 256 threads: warp w owns local-j [w*8, w*8+8); lane: b_loc = lane&7,
// js = lane>>3 -> thread computes the pair (jj0, jj0+1), jj0 = w*8 + js*2,
// as one f32x2 accumulator chain set (4 independent chains).

#define CL      8
#define JS      64
#define BG      8
#define HPAD    516
#define WSTRIDE 66
#define HBUF_F  (BG * HPAD)            // floats per h buffer
#define HBUF_B  (HBUF_F * 4)           // bytes per h buffer
#define SMEM_C  ((HH * WSTRIDE + 2 * HBUF_F) * 4)

__global__ void __cluster_dims__(CL, 1, 1) __launch_bounds__(256, 1)
rnn_scan_kernel(float* __restrict__ out, const float* __restrict__ W_hh,
                const int* __restrict__ lengths)
{
    extern __shared__ float smem[];
    float* Wt = smem;                         // HH * WSTRIDE floats
    float* hbuf = smem + HH * WSTRIDE;        // 2 * HBUF_F floats

    const int tid = threadIdx.x;
    const unsigned rank = cluster_rank();
    const int cid = blockIdx.x / CL;

    // Load + transpose this CTA's W_hh slice: Wt[k][jj] = W_hh[rank*64+jj][k]
    for (int idx = tid; idx < JS * HH; idx += 256) {
        int jj = idx >> 9;         // /512
        int k = idx & (HH - 1);
        Wt[k * WSTRIDE + jj] = W_hh[(rank * JS + jj) * HH + k];
    }
    // Zero buffer 0 (h at t=0)
    for (int idx = tid; idx < HBUF_F; idx += 256) hbuf[idx] = 0.0f;

    const int warp = tid >> 5, lane = tid & 31;
    const int b_loc = lane & 7;
    const int js = lane >> 3;
    const int jj0 = warp * 8 + js * 2;
    const int b = cid * BG + b_loc;
    const int len = lengths[b];
    const int jglob = (int)rank * JS + jj0;

    const float2 cpv = *(const float2*)&g_cp[b * HH + jglob];

    float* outp = out + (size_t)b * TT * HH + jglob;
    float* lastp = out + (size_t)BB * TT * HH + (size_t)b * HH + jglob;

    const unsigned h_region = smem_u32(hbuf);
    const unsigned my_off = (unsigned)((b_loc * HPAD + jglob) * 4);
    unsigned dsta[CL];
#pragma unroll
    for (int r = 0; r < CL; r++) dsta[r] = mapa_cluster(h_region + my_off, (unsigned)r);

    const unsigned hread_base = h_region + (unsigned)(b_loc * HPAD * 4);
    const unsigned wbase = smem_u32(Wt) + (unsigned)(jj0 * 4);

    cluster_sync_();

    for (int t = 0; t < TT; t++) {
        const int p = t & 1;                 // read buffer
        const unsigned roff = (unsigned)p * HBUF_B;
        const unsigned woff = (unsigned)(p ^ 1) * HBUF_B;

        // xp for this step (issued early; consumed after the dot)
        float2 xp = *(const float2*)outp;

        unsigned hptr = hread_base + roff;
        unsigned wptr = wbase;
        unsigned long long a0 = 0ull, a1 = 0ull, a2 = 0ull, a3 = 0ull;
#pragma unroll 4
        for (int k = 0; k < HH; k += 4) {
            float4 h4 = lds128v(hptr);
            unsigned long long w0 = lds64v(wptr);
            unsigned long long w1 = lds64v(wptr + WSTRIDE * 4);
            unsigned long long w2 = lds64v(wptr + 2 * WSTRIDE * 4);
            unsigned long long w3 = lds64v(wptr + 3 * WSTRIDE * 4);
            fma2(a0, w0, dup2(h4.x));
            fma2(a1, w1, dup2(h4.y));
            fma2(a2, w2, dup2(h4.z));
            fma2(a3, w3, dup2(h4.w));
            hptr += 16;
            wptr += 4 * WSTRIDE * 4;
        }
        float2 a = unpack2(add2(add2(a0, a1), add2(a2, a3)));

        // previous h for this thread's own slice (for masked carry)
        float2 hold = unpack2(lds64v(hread_base + roff + (unsigned)(jglob * 4)));

        const bool active = (t < len);
        float v0 = tanhf(a.x + xp.x + cpv.x);
        float v1 = tanhf(a.y + xp.y + cpv.y);
        float n0 = active ? v0 : hold.x;
        float n1 = active ? v1 : hold.y;

        float2 o = active ? make_float2(v0, v1) : make_float2(0.0f, 0.0f);
        *(float2*)outp = o;
        if (t == len - 1) *(float2*)lastp = make_float2(v0, v1);

        const unsigned long long hn = pack2(n0, n1);
#pragma unroll
        for (int r = 0; r < CL; r++) st_cluster64(dsta[r] + woff, hn);

        outp += HH;
        cluster_sync_();
    }
}

// ---------------- launch -------------------------------------------------------

extern "C" void kernel_launch(void* const* d_in, const int* in_sizes, int n_in,
                              void* d_out, int out_size)
{
    const float* x       = (const float*)d_in[0];
    const float* cons    = (const float*)d_in[1];
    const int*   lengths = (const int*)d_in[2];
    const float* W_ih    = (const float*)d_in[3];
    const float* b_ih    = (const float*)d_in[4];
    const float* W_hh    = (const float*)d_in[5];
    const float* b_hh    = (const float*)d_in[6];
    const float* W_ch    = (const float*)d_in[7];
    const float* b_ch    = (const float*)d_in[8];
    float* out = (float*)d_out;

    // Phase A: xp into the outputs region of d_out
    dim3 ga((BB * TT) / 64, HH / 64);
    xp_gemm_kernel<<<ga, 256>>>(x, W_ih, b_ih, out);

    // Phase B: cp
    cp_kernel<<<BB, HH>>>(cons, W_ch, b_ch, b_hh);

    // Phase C: recurrence (cluster kernel, big dynamic SMEM)
    cudaFuncSetAttribute(rnn_scan_kernel,
                         cudaFuncAttributeMaxDynamicSharedMemorySize, SMEM_C);
    rnn_scan_kernel<<<BB, 256, SMEM_C>>>(out, W_hh, lengths);
}

// round 2
// speedup vs baseline: 1.0156x; 1.0156x over previous
#include <cuda_runtime.h>
#include <cuda_bf16.h>
#include <cstdint>

// Problem constants
#define BB   128
#define TT   1024
#define II   256
#define HH   512
#define CC   32

typedef unsigned long long ull;

// ---------------- f32x2 / SMEM asm helpers ----------------

__device__ __forceinline__ unsigned smem_u32(const void* p) {
    return (unsigned)__cvta_generic_to_shared(p);
}

__device__ __forceinline__ ull lds64v(unsigned a) {
    ull v;
    asm volatile("ld.shared.b64 %0, [%1];" : "=l"(v) : "r"(a));
    return v;
}

__device__ __forceinline__ void lds_v2u64(unsigned a, ull& x, ull& y) {
    asm volatile("ld.shared.v2.u64 {%0,%1}, [%2];" : "=l"(x), "=l"(y) : "r"(a));
}

__device__ __forceinline__ float4 lds128v(unsigned a) {
    float4 v;
    asm volatile("ld.shared.v4.f32 {%0,%1,%2,%3}, [%4];"
                 : "=f"(v.x), "=f"(v.y), "=f"(v.z), "=f"(v.w) : "r"(a));
    return v;
}

__device__ __forceinline__ ull dup2(float x) {
    unsigned xi = __float_as_uint(x);
    ull v;
    asm("mov.b64 %0, {%1, %1};" : "=l"(v) : "r"(xi));
    return v;
}

__device__ __forceinline__ ull pack2(float x, float y) {
    unsigned xi = __float_as_uint(x), yi = __float_as_uint(y);
    ull v;
    asm("mov.b64 %0, {%1, %2};" : "=l"(v) : "r"(xi), "r"(yi));
    return v;
}

__device__ __forceinline__ float2 unpack2(ull v) {
    unsigned a, b;
    asm("mov.b64 {%0, %1}, %2;" : "=r"(a), "=r"(b) : "l"(v));
    return make_float2(__uint_as_float(a), __uint_as_float(b));
}

__device__ __forceinline__ void fma2(ull& acc, ull a, ull b) {
    asm("fma.rn.f32x2 %0, %1, %2, %0;" : "+l"(acc) : "l"(a), "l"(b));
}

__device__ __forceinline__ ull add2(ull a, ull b) {
    ull d;
    asm("add.rn.f32x2 %0, %1, %2;" : "=l"(d) : "l"(a), "l"(b));
    return d;
}

__device__ __forceinline__ unsigned mapa_cluster(unsigned addr, unsigned rank) {
    unsigned r;
    asm("mapa.shared::cluster.u32 %0, %1, %2;" : "=r"(r) : "r"(addr), "r"(rank));
    return r;
}

__device__ __forceinline__ void st_cluster64(unsigned addr, ull v) {
    asm volatile("st.shared::cluster.b64 [%0], %1;" :: "r"(addr), "l"(v) : "memory");
}

__device__ __forceinline__ unsigned cluster_rank() {
    unsigned r;
    asm("mov.u32 %0, %%cluster_ctarank;" : "=r"(r));
    return r;
}

__device__ __forceinline__ void cluster_sync_() {
    asm volatile("barrier.cluster.arrive.aligned;" ::: "memory");
    asm volatile("barrier.cluster.wait.aligned;" ::: "memory");
}

// ---------------- Kernel A: xp = x @ W_ih^T + b_ih -> out[(b*T+t)*H + h] --------
// 64x64 block tile, 16-deep K tiles, 256 threads, 4m x 4n per thread via FFMA2.
// Register-prefetch of the next k-tile overlaps global latency with compute.

__global__ void __launch_bounds__(256)
xp_gemm_kernel(const float* __restrict__ x, const float* __restrict__ W,
               const float* __restrict__ bias, float* __restrict__ out)
{
    __shared__ float As[16][64];   // [k][m]
    __shared__ float Bs[16][64];   // [k][h]

    const int tid = threadIdx.x;
    const int m0 = blockIdx.x * 64;
    const int h0 = blockIdx.y * 64;
    const int tx = tid & 15;       // n group
    const int ty = tid >> 4;       // m group
    const int ml = tid >> 2;       // staging row 0..63
    const int kl = (tid & 3) * 4;  // staging k offset

    ull acc[4][2];
#pragma unroll
    for (int i = 0; i < 4; i++) { acc[i][0] = 0ull; acc[i][1] = 0ull; }

    const float* xg = x + (size_t)(m0 + ml) * II + kl;
    const float* wg = W + (size_t)(h0 + ml) * II + kl;
    const unsigned aAddr = smem_u32(&As[0][ty * 4]);
    const unsigned bAddr = smem_u32(&Bs[0][tx * 4]);

    float4 xv = *(const float4*)(xg);
    float4 wv = *(const float4*)(wg);

    for (int kt = 0; kt < II; kt += 16) {
        __syncthreads();
        As[kl + 0][ml] = xv.x; As[kl + 1][ml] = xv.y;
        As[kl + 2][ml] = xv.z; As[kl + 3][ml] = xv.w;
        Bs[kl + 0][ml] = wv.x; Bs[kl + 1][ml] = wv.y;
        Bs[kl + 2][ml] = wv.z; Bs[kl + 3][ml] = wv.w;
        __syncthreads();
        if (kt + 16 < II) {
            xv = *(const float4*)(xg + kt + 16);
            wv = *(const float4*)(wg + kt + 16);
        }
#pragma unroll
        for (int k = 0; k < 16; k++) {
            float4 a4 = lds128v(aAddr + (unsigned)(k * 256));
            ull b01 = lds64v(bAddr + (unsigned)(k * 256));
            ull b23 = lds64v(bAddr + (unsigned)(k * 256 + 8));
            ull d;
            d = dup2(a4.x); fma2(acc[0][0], b01, d); fma2(acc[0][1], b23, d);
            d = dup2(a4.y); fma2(acc[1][0], b01, d); fma2(acc[1][1], b23, d);
            d = dup2(a4.z); fma2(acc[2][0], b01, d); fma2(acc[2][1], b23, d);
            d = dup2(a4.w); fma2(acc[3][0], b01, d); fma2(acc[3][1], b23, d);
        }
    }

    const float2 bias01 = *(const float2*)&bias[h0 + tx * 4];
    const float2 bias23 = *(const float2*)&bias[h0 + tx * 4 + 2];
#pragma unroll
    for (int i = 0; i < 4; i++) {
        float2 c01 = unpack2(acc[i][0]);
        float2 c23 = unpack2(acc[i][1]);
        float4 res;
        res.x = c01.x + bias01.x;
        res.y = c01.y + bias01.y;
        res.z = c23.x + bias23.x;
        res.w = c23.y + bias23.y;
        *(float4*)&out[(size_t)(m0 + ty * 4 + i) * HH + h0 + tx * 4] = res;
    }
}

// ---------------- Kernel B: cp[b][h] = constraints[b]@W_ch[h] + b_ch[h] + b_hh[h]

__device__ float g_cp[BB * HH];

__global__ void __launch_bounds__(512)
cp_kernel(const float* __restrict__ cons, const float* __restrict__ W_ch,
          const float* __restrict__ b_ch, const float* __restrict__ b_hh)
{
    __shared__ float cs[CC];
    const int b = blockIdx.x;
    const int h = threadIdx.x;
    if (h < CC) cs[h] = cons[b * CC + h];
    __syncthreads();
    float s = b_ch[h] + b_hh[h];
#pragma unroll
    for (int c = 0; c < CC; c++) s += cs[c] * W_ch[h * CC + c];
    g_cp[b * HH + h] = s;
}

// ---------------- Kernel C: sequential recurrence -----------------------------
// Cluster of 8 CTAs; CTA rank r holds W_hh rows [r*64, r*64+64) in SMEM in
// row-major [j][k] layout (stride KPAD=516 floats -> conflict-free f32x2-over-k
// vector loads). h double-buffered per CTA as [b][k] (stride 516). Each step:
// thread computes dot products for j-pair (j0, j0+1) for one batch row with
// f32x2 accumulation over even/odd k; results broadcast to all 8 CTAs via
// DSMEM stores; one cluster barrier per step.

#define CL      8
#define JS      64
#define BG      8
#define KPAD    516
#define HPAD    516
#define HBUF_F  (BG * HPAD)            // floats per h buffer
#define HBUF_B  (HBUF_F * 4)           // bytes per h buffer
#define SMEM_C  ((JS * KPAD + 2 * HBUF_F) * 4)

__global__ void __cluster_dims__(CL, 1, 1) __launch_bounds__(256, 1)
rnn_scan_kernel(float* __restrict__ out, const float* __restrict__ W_hh,
                const int* __restrict__ lengths)
{
    extern __shared__ float smem[];
    float* Wt = smem;                         // JS * KPAD floats, [j][k]
    float* hbuf = smem + JS * KPAD;           // 2 * HBUF_F floats, [b][k]

    const int tid = threadIdx.x;
    const unsigned rank = cluster_rank();
    const int cid = blockIdx.x / CL;

    // Load this CTA's W_hh slice: Wt[jj][k] = W_hh[rank*64+jj][k] (coalesced)
    for (int idx = tid; idx < JS * HH; idx += 256) {
        int jj = idx >> 9;         // /512
        int k = idx & (HH - 1);
        Wt[jj * KPAD + k] = W_hh[(rank * JS + jj) * HH + k];
    }
    // Zero buffer 0 (h at t=0)
    for (int idx = tid; idx < HBUF_F; idx += 256) hbuf[idx] = 0.0f;

    const int warp = tid >> 5, lane = tid & 31;
    const int b_loc = lane & 7;
    const int js = lane >> 3;
    const int j0 = warp * 8 + js * 2;   // even; pair (j0, j0+1)
    const int b = cid * BG + b_loc;
    const int len = lengths[b];
    const int jglob = (int)rank * JS + j0;

    const float2 cpv = *(const float2*)&g_cp[b * HH + jglob];

    float* outp = out + (size_t)b * TT * HH + jglob;
    float* lastp = out + (size_t)BB * TT * HH + (size_t)b * HH + jglob;

    const unsigned h_region = smem_u32(hbuf);
    const unsigned my_off = (unsigned)((b_loc * HPAD + jglob) * 4);
    unsigned dsta[CL];
#pragma unroll
    for (int r = 0; r < CL; r++) dsta[r] = mapa_cluster(h_region + my_off, (unsigned)r);

    const unsigned hread_base = h_region + (unsigned)(b_loc * HPAD * 4);
    const unsigned w0base = smem_u32(Wt) + (unsigned)(j0 * KPAD * 4);
    const unsigned w1base = w0base + (unsigned)(KPAD * 4);

    cluster_sync_();

    for (int t = 0; t < TT; t++) {
        const int p = t & 1;                 // read buffer
        const unsigned roff = (unsigned)p * HBUF_B;
        const unsigned woff = (unsigned)(p ^ 1) * HBUF_B;

        // xp for this step (issued early; consumed after the dot)
        float2 xp = *(const float2*)outp;

        const unsigned hb = hread_base + roff;
        ull a00 = 0ull, a01 = 0ull, a10 = 0ull, a11 = 0ull;
#pragma unroll 16
        for (int k = 0; k < HH; k += 4) {
            ull h0, h1, wa0, wa1, wb0, wb1;
            lds_v2u64(hb + (unsigned)(k * 4), h0, h1);
            lds_v2u64(w0base + (unsigned)(k * 4), wa0, wa1);
            lds_v2u64(w1base + (unsigned)(k * 4), wb0, wb1);
            fma2(a00, wa0, h0);
            fma2(a01, wa1, h1);
            fma2(a10, wb0, h0);
            fma2(a11, wb1, h1);
        }
        float2 s0 = unpack2(add2(a00, a01));
        float2 s1 = unpack2(add2(a10, a11));
        float d0 = s0.x + s0.y;              // dot for j0
        float d1 = s1.x + s1.y;              // dot for j0+1

        // previous h for this thread's own slice (for masked carry)
        float2 hold = unpack2(lds64v(hb + (unsigned)(jglob * 4)));

        const bool active = (t < len);
        float v0 = tanhf(d0 + xp.x + cpv.x);
        float v1 = tanhf(d1 + xp.y + cpv.y);
        float n0 = active ? v0 : hold.x;
        float n1 = active ? v1 : hold.y;

        float2 o = active ? make_float2(v0, v1) : make_float2(0.0f, 0.0f);
        *(float2*)outp = o;
        if (t == len - 1) *(float2*)lastp = make_float2(v0, v1);

        const ull hn = pack2(n0, n1);
#pragma unroll
        for (int r = 0; r < CL; r++) st_cluster64(dsta[r] + woff, hn);

        outp += HH;
        cluster_sync_();
    }
}

// ---------------- launch -------------------------------------------------------

extern "C" void kernel_launch(void* const* d_in, const int* in_sizes, int n_in,
                              void* d_out, int out_size)
{
    const float* x       = (const float*)d_in[0];
    const float* cons    = (const float*)d_in[1];
    const int*   lengths = (const int*)d_in[2];
    const float* W_ih    = (const float*)d_in[3];
    const float* b_ih    = (const float*)d_in[4];
    const float* W_hh    = (const float*)d_in[5];
    const float* b_hh    = (const float*)d_in[6];
    const float* W_ch    = (const float*)d_in[7];
    const float* b_ch    = (const float*)d_in[8];
    float* out = (float*)d_out;

    // Phase A: xp into the outputs region of d_out
    dim3 ga((BB * TT) / 64, HH / 64);
    xp_gemm_kernel<<<ga, 256>>>(x, W_ih, b_ih, out);

    // Phase B: cp
    cp_kernel<<<BB, HH>>>(cons, W_ch, b_ch, b_hh);

    // Phase C: recurrence (cluster kernel, big dynamic SMEM)
    cudaFuncSetAttribute(rnn_scan_kernel,
                         cudaFuncAttributeMaxDynamicSharedMemorySize, SMEM_C);
    rnn_scan_kernel<<<BB, 256, SMEM_C>>>(out, W_hh, lengths);
}

// round 3
// speedup vs baseline: 1.0442x; 1.0281x over previous
#include <cuda_runtime.h>
#include <cuda_bf16.h>
#include <cstdint>

// Problem constants
#define BB   128
#define TT   1024
#define II   256
#define HH   512
#define CC   32

#define GR   8          // CTAs per group (W split 8 ways)
#define NG   (BB / GR)  // 16 groups, 8 batches each
#define BG   8          // batches per group
#define JS   64         // j rows per CTA
#define KPAD 516        // padded row stride (floats) for conflict-free LDS

typedef unsigned long long ull;

// ---------------- f32x2 / SMEM asm helpers ----------------

__device__ __forceinline__ unsigned smem_u32(const void* p) {
    return (unsigned)__cvta_generic_to_shared(p);
}

__device__ __forceinline__ ull lds64v(unsigned a) {
    ull v;
    asm volatile("ld.shared.b64 %0, [%1];" : "=l"(v) : "r"(a));
    return v;
}

__device__ __forceinline__ void lds_v2u64(unsigned a, ull& x, ull& y) {
    asm volatile("ld.shared.v2.u64 {%0,%1}, [%2];" : "=l"(x), "=l"(y) : "r"(a));
}

__device__ __forceinline__ float4 lds128v(unsigned a) {
    float4 v;
    asm volatile("ld.shared.v4.f32 {%0,%1,%2,%3}, [%4];"
                 : "=f"(v.x), "=f"(v.y), "=f"(v.z), "=f"(v.w) : "r"(a));
    return v;
}

__device__ __forceinline__ ull dup2(float x) {
    unsigned xi = __float_as_uint(x);
    ull v;
    asm("mov.b64 %0, {%1, %1};" : "=l"(v) : "r"(xi));
    return v;
}

__device__ __forceinline__ float2 unpack2(ull v) {
    unsigned a, b;
    asm("mov.b64 {%0, %1}, %2;" : "=r"(a), "=r"(b) : "l"(v));
    return make_float2(__uint_as_float(a), __uint_as_float(b));
}

__device__ __forceinline__ void fma2(ull& acc, ull a, ull b) {
    asm("fma.rn.f32x2 %0, %1, %2, %0;" : "+l"(acc) : "l"(a), "l"(b));
}

__device__ __forceinline__ ull add2(ull a, ull b) {
    ull d;
    asm("add.rn.f32x2 %0, %1, %2;" : "=l"(d) : "l"(a), "l"(b));
    return d;
}

// ---------------- Kernel A: xp = x @ W_ih^T + b_ih -> out[(b*T+t)*H + h] --------

__global__ void __launch_bounds__(256)
xp_gemm_kernel(const float* __restrict__ x, const float* __restrict__ W,
               const float* __restrict__ bias, float* __restrict__ out)
{
    __shared__ float As[16][64];   // [k][m]
    __shared__ float Bs[16][64];   // [k][h]

    const int tid = threadIdx.x;
    const int m0 = blockIdx.x * 64;
    const int h0 = blockIdx.y * 64;
    const int tx = tid & 15;       // n group
    const int ty = tid >> 4;       // m group
    const int ml = tid >> 2;       // staging row 0..63
    const int kl = (tid & 3) * 4;  // staging k offset

    ull acc[4][2];
#pragma unroll
    for (int i = 0; i < 4; i++) { acc[i][0] = 0ull; acc[i][1] = 0ull; }

    const float* xg = x + (size_t)(m0 + ml) * II + kl;
    const float* wg = W + (size_t)(h0 + ml) * II + kl;
    const unsigned aAddr = smem_u32(&As[0][ty * 4]);
    const unsigned bAddr = smem_u32(&Bs[0][tx * 4]);

    float4 xv = *(const float4*)(xg);
    float4 wv = *(const float4*)(wg);

    for (int kt = 0; kt < II; kt += 16) {
        __syncthreads();
        As[kl + 0][ml] = xv.x; As[kl + 1][ml] = xv.y;
        As[kl + 2][ml] = xv.z; As[kl + 3][ml] = xv.w;
        Bs[kl + 0][ml] = wv.x; Bs[kl + 1][ml] = wv.y;
        Bs[kl + 2][ml] = wv.z; Bs[kl + 3][ml] = wv.w;
        __syncthreads();
        if (kt + 16 < II) {
            xv = *(const float4*)(xg + kt + 16);
            wv = *(const float4*)(wg + kt + 16);
        }
#pragma unroll
        for (int k = 0; k < 16; k++) {
            float4 a4 = lds128v(aAddr + (unsigned)(k * 256));
            ull b01 = lds64v(bAddr + (unsigned)(k * 256));
            ull b23 = lds64v(bAddr + (unsigned)(k * 256 + 8));
            ull d;
            d = dup2(a4.x); fma2(acc[0][0], b01, d); fma2(acc[0][1], b23, d);
            d = dup2(a4.y); fma2(acc[1][0], b01, d); fma2(acc[1][1], b23, d);
            d = dup2(a4.z); fma2(acc[2][0], b01, d); fma2(acc[2][1], b23, d);
            d = dup2(a4.w); fma2(acc[3][0], b01, d); fma2(acc[3][1], b23, d);
        }
    }

    const float2 bias01 = *(const float2*)&bias[h0 + tx * 4];
    const float2 bias23 = *(const float2*)&bias[h0 + tx * 4 + 2];
#pragma unroll
    for (int i = 0; i < 4; i++) {
        float2 c01 = unpack2(acc[i][0]);
        float2 c23 = unpack2(acc[i][1]);
        float4 res;
        res.x = c01.x + bias01.x;
        res.y = c01.y + bias01.y;
        res.z = c23.x + bias23.x;
        res.w = c23.y + bias23.y;
        *(float4*)&out[(size_t)(m0 + ty * 4 + i) * HH + h0 + tx * 4] = res;
    }
}

// ---------------- Kernel B: cp[b][h] = constraints[b]@W_ch[h] + b_ch[h] + b_hh[h]

__device__ float g_cp[BB * HH];
__device__ float g_h[2][BB][HH];        // h exchange buffers (L2)
__device__ int   g_cnt[2][NG][32];      // group arrival counters, 128B padded

__global__ void __launch_bounds__(512)
cp_kernel(const float* __restrict__ cons, const float* __restrict__ W_ch,
          const float* __restrict__ b_ch, const float* __restrict__ b_hh)
{
    __shared__ float cs[CC];
    const int b = blockIdx.x;
    const int h = threadIdx.x;
    if (h < CC) cs[h] = cons[b * CC + h];
    __syncthreads();
    float s = b_ch[h] + b_hh[h];
#pragma unroll
    for (int c = 0; c < CC; c++) s += cs[c] * W_ch[h * CC + c];
    g_cp[b * HH + h] = s;
}

// ---------------- Kernel C: sequential recurrence (no clusters) ----------------
// 128 plain CTAs, 1/SM. Group g = 8 CTAs handling batches [8g, 8g+8); CTA r of
// the group holds W_hh rows [64r, 64r+64) in SMEM. Per step: dot from SMEM h
// stage, tanh, STG h-slice to g_h (L2), group sync via release-add/acquire-poll
// counter, fence (L1 invalidate), re-stage 16KB h from L2 into SMEM. Double
// buffered in both SMEM and global.

#define SMEM_C  ((JS * KPAD + 2 * BG * KPAD) * 4)

__global__ void __launch_bounds__(256, 1)
rnn_scan_kernel(float* __restrict__ out, const float* __restrict__ W_hh,
                const int* __restrict__ lengths)
{
    extern __shared__ float smem[];
    float* Wt = smem;                         // JS * KPAD floats, [j][k]
    float* hS = smem + JS * KPAD;             // 2 * BG * KPAD floats, [w][b][k]

    const int tid = threadIdx.x;
    const int r = blockIdx.x & 7;             // rank in group
    const int g = blockIdx.x >> 3;            // group

    // Load this CTA's W_hh slice: Wt[jj][k] = W_hh[r*64+jj][k] (coalesced)
    for (int idx = tid; idx < JS * HH; idx += 256) {
        int jj = idx >> 9;
        int k = idx & (HH - 1);
        Wt[jj * KPAD + k] = W_hh[(r * JS + jj) * HH + k];
    }
    // Zero phase-0 h stage (h at t=0)
    for (int idx = tid; idx < BG * KPAD; idx += 256) hS[idx] = 0.0f;

    const int warp = tid >> 5, lane = tid & 31;
    const int b_loc = lane & 7;
    const int js = lane >> 3;
    const int j0 = warp * 8 + js * 2;          // pair (j0, j0+1)
    const int b = g * BG + b_loc;
    const int len = lengths[b];
    const int jglob = r * JS + j0;

    const float2 cpv = *(const float2*)&g_cp[b * HH + jglob];

    float* outp = out + (size_t)b * TT * HH + jglob;
    float* lastp = out + (size_t)BB * TT * HH + (size_t)b * HH + jglob;
    int* cnt1 = &g_cnt[1][g][0];
    int* cnt0 = &g_cnt[0][g][0];

    const unsigned hbase = smem_u32(hS) + (unsigned)(b_loc * KPAD * 4);
    const unsigned w0base = smem_u32(Wt) + (unsigned)(j0 * KPAD * 4);
    const unsigned w1base = w0base + (unsigned)(KPAD * 4);

    __syncthreads();

    for (int t = 0; t < TT; t++) {
        const int p = t & 1;                  // read phase
        const int w = p ^ 1;                  // write phase
        const unsigned roff = (unsigned)p * (BG * KPAD * 4);

        float2 xp = *(const float2*)outp;     // consumed after the dot loop

        const unsigned hb = hbase + roff;
        ull a00 = 0ull, a01 = 0ull, a10 = 0ull, a11 = 0ull;
#pragma unroll 8
        for (int k = 0; k < HH; k += 4) {
            ull h0, h1, wa0, wa1, wb0, wb1;
            lds_v2u64(hb + (unsigned)(k * 4), h0, h1);
            lds_v2u64(w0base + (unsigned)(k * 4), wa0, wa1);
            lds_v2u64(w1base + (unsigned)(k * 4), wb0, wb1);
            fma2(a00, wa0, h0);
            fma2(a01, wa1, h1);
            fma2(a10, wb0, h0);
            fma2(a11, wb1, h1);
        }
        float2 s0 = unpack2(add2(a00, a01));
        float2 s1 = unpack2(add2(a10, a11));
        float d0 = s0.x + s0.y;
        float d1 = s1.x + s1.y;

        float2 hold = unpack2(lds64v(hb + (unsigned)(jglob * 4)));

        const bool active = (t < len);
        float v0 = tanhf(d0 + xp.x + cpv.x);
        float v1 = tanhf(d1 + xp.y + cpv.y);
        float n0 = active ? v0 : hold.x;
        float n1 = active ? v1 : hold.y;

        // publish h slice to L2 first (on the critical sync path)
        *(float2*)&g_h[w][b][jglob] = make_float2(n0, n1);

        float2 o = active ? make_float2(v0, v1) : make_float2(0.0f, 0.0f);
        *(float2*)outp = o;
        if (t == len - 1) *(float2*)lastp = make_float2(v0, v1);
        outp += HH;

        if (t == TT - 1) break;

        __syncthreads();                       // all stores issued
        if (tid == 0) {
            int* cw = w ? cnt1 : cnt0;
            asm volatile("red.release.gpu.global.add.s32 [%0], %1;"
                         :: "l"(cw), "r"(1) : "memory");
            const int target = ((t >> 1) + 1) * GR;
            int v;
            do {
                asm volatile("ld.acquire.gpu.global.s32 %0, [%1];"
                             : "=r"(v) : "l"(cw) : "memory");
            } while (v < target);
            asm volatile("fence.acq_rel.gpu;" ::: "memory");
        }
        __syncthreads();                       // sync + L1 invalidated

        // stage full h for this group's 8 batches: 8 x 512 floats from L2
#pragma unroll
        for (int i = 0; i < 4; i++) {
            int idx = tid + i * 256;           // 1024 float4 total
            int b_i = idx >> 7;                // 0..7
            int k_i = (idx & 127) * 4;         // 0..508
            float4 v4 = *(const float4*)&g_h[w][g * BG + b_i][k_i];
            *(float4*)&hS[(w * BG + b_i) * KPAD + k_i] = v4;
        }
        __syncthreads();                       // stage visible to all
    }
}

// ---------------- launch -------------------------------------------------------

extern "C" void kernel_launch(void* const* d_in, const int* in_sizes, int n_in,
                              void* d_out, int out_size)
{
    const float* x       = (const float*)d_in[0];
    const float* cons    = (const float*)d_in[1];
    const int*   lengths = (const int*)d_in[2];
    const float* W_ih    = (const float*)d_in[3];
    const float* b_ih    = (const float*)d_in[4];
    const float* W_hh    = (const float*)d_in[5];
    const float* b_hh    = (const float*)d_in[6];
    const float* W_ch    = (const float*)d_in[7];
    const float* b_ch    = (const float*)d_in[8];
    float* out = (float*)d_out;

    // Reset group counters (graph-capturable memset node)
    void* cnt_addr = nullptr;
    cudaGetSymbolAddress(&cnt_addr, g_cnt);
    cudaMemsetAsync(cnt_addr, 0, sizeof(int) * 2 * NG * 32);

    // Phase A: xp into the outputs region of d_out
    dim3 ga((BB * TT) / 64, HH / 64);
    xp_gemm_kernel<<<ga, 256>>>(x, W_ih, b_ih, out);

    // Phase B: cp
    cp_kernel<<<BB, HH>>>(cons, W_ch, b_ch, b_hh);

    // Phase C: recurrence (plain 128-CTA persistent-style kernel)
    cudaFuncSetAttribute(rnn_scan_kernel,
                         cudaFuncAttributeMaxDynamicSharedMemorySize, SMEM_C);
    rnn_scan_kernel<<<BB, 256, SMEM_C>>>(out, W_hh, lengths);
}

// round 4
// speedup vs baseline: 2.0376x; 1.9514x over previous
#include <cuda_runtime.h>
#include <cuda_bf16.h>
#include <cstdint>

// Problem constants
#define BB   128
#define TT   1024
#define II   256
#define HH   512
#define CC   32

#define GR   8          // CTAs per group (W split 8 ways)
#define NG   (BB / GR)  // 16 groups
#define BG   8          // batches per group
#define JS   64         // j rows per CTA

// scan smem geometry (units: 32-bit words)
#define SLS   34                      // words per 32-float k-slice (2 pad)
#define ROWW  (16 * SLS)              // 544 words per 512-float row
#define WT_WORDS (JS * ROWW)          // 34816
#define HBUF_W   (BG * ROWW)          // 4352 words per h phase
#define PART_OFF (WT_WORDS + 2 * HBUF_W)   // 43520
#define RPS   10                      // partial row stride (4 f32x2 + pad)
#define SMEM_C ((PART_OFF + 512 * RPS) * 4) // 194560 bytes

typedef unsigned long long ull;

// ---------------- asm helpers ----------------

__device__ __forceinline__ unsigned smem_u32(const void* p) {
    return (unsigned)__cvta_generic_to_shared(p);
}

__device__ __forceinline__ ull lds64v(unsigned a) {
    ull v;
    asm volatile("ld.shared.b64 %0, [%1];" : "=l"(v) : "r"(a));
    return v;
}

__device__ __forceinline__ void sts64v(unsigned a, ull v) {
    asm volatile("st.shared.b64 [%0], %1;" :: "r"(a), "l"(v) : "memory");
}

__device__ __forceinline__ float lds32v(unsigned a) {
    float v;
    asm volatile("ld.shared.f32 %0, [%1];" : "=f"(v) : "r"(a));
    return v;
}

__device__ __forceinline__ float4 lds128v(unsigned a) {
    float4 v;
    asm volatile("ld.shared.v4.f32 {%0,%1,%2,%3}, [%4];"
                 : "=f"(v.x), "=f"(v.y), "=f"(v.z), "=f"(v.w) : "r"(a));
    return v;
}

__device__ __forceinline__ ull dup2(float x) {
    unsigned xi = __float_as_uint(x);
    ull v;
    asm("mov.b64 %0, {%1, %1};" : "=l"(v) : "r"(xi));
    return v;
}

__device__ __forceinline__ float2 unpack2(ull v) {
    unsigned a, b;
    asm("mov.b64 {%0, %1}, %2;" : "=r"(a), "=r"(b) : "l"(v));
    return make_float2(__uint_as_float(a), __uint_as_float(b));
}

__device__ __forceinline__ void fma2(ull& acc, ull a, ull b) {
    asm("fma.rn.f32x2 %0, %1, %2, %0;" : "+l"(acc) : "l"(a), "l"(b));
}

__device__ __forceinline__ ull add2(ull a, ull b) {
    ull d;
    asm("add.rn.f32x2 %0, %1, %2;" : "=l"(d) : "l"(a), "l"(b));
    return d;
}

// ---------------- dummy kernels (shift ncu capture onto the scan kernel) -------

__global__ void noop_kernel_a() {}
__global__ void noop_kernel_b() {}

// ---------------- Kernel A: xp = x @ W_ih^T + b_ih -> out[(b*T+t)*H + h] --------

__global__ void __launch_bounds__(256)
xp_gemm_kernel(const float* __restrict__ x, const float* __restrict__ W,
               const float* __restrict__ bias, float* __restrict__ out)
{
    __shared__ float As[16][64];
    __shared__ float Bs[16][64];

    const int tid = threadIdx.x;
    const int m0 = blockIdx.x * 64;
    const int h0 = blockIdx.y * 64;
    const int tx = tid & 15;
    const int ty = tid >> 4;
    const int ml = tid >> 2;
    const int kl = (tid & 3) * 4;

    ull acc[4][2];
#pragma unroll
    for (int i = 0; i < 4; i++) { acc[i][0] = 0ull; acc[i][1] = 0ull; }

    const float* xg = x + (size_t)(m0 + ml) * II + kl;
    const float* wg = W + (size_t)(h0 + ml) * II + kl;
    const unsigned aAddr = smem_u32(&As[0][ty * 4]);
    const unsigned bAddr = smem_u32(&Bs[0][tx * 4]);

    float4 xv = *(const float4*)(xg);
    float4 wv = *(const float4*)(wg);

    for (int kt = 0; kt < II; kt += 16) {
        __syncthreads();
        As[kl + 0][ml] = xv.x; As[kl + 1][ml] = xv.y;
        As[kl + 2][ml] = xv.z; As[kl + 3][ml] = xv.w;
        Bs[kl + 0][ml] = wv.x; Bs[kl + 1][ml] = wv.y;
        Bs[kl + 2][ml] = wv.z; Bs[kl + 3][ml] = wv.w;
        __syncthreads();
        if (kt + 16 < II) {
            xv = *(const float4*)(xg + kt + 16);
            wv = *(const float4*)(wg + kt + 16);
        }
#pragma unroll
        for (int k = 0; k < 16; k++) {
            float4 a4 = lds128v(aAddr + (unsigned)(k * 256));
            ull b01 = lds64v(bAddr + (unsigned)(k * 256));
            ull b23 = lds64v(bAddr + (unsigned)(k * 256 + 8));
            ull d;
            d = dup2(a4.x); fma2(acc[0][0], b01, d); fma2(acc[0][1], b23, d);
            d = dup2(a4.y); fma2(acc[1][0], b01, d); fma2(acc[1][1], b23, d);
            d = dup2(a4.z); fma2(acc[2][0], b01, d); fma2(acc[2][1], b23, d);
            d = dup2(a4.w); fma2(acc[3][0], b01, d); fma2(acc[3][1], b23, d);
        }
    }

    const float2 bias01 = *(const float2*)&bias[h0 + tx * 4];
    const float2 bias23 = *(const float2*)&bias[h0 + tx * 4 + 2];
#pragma unroll
    for (int i = 0; i < 4; i++) {
        float2 c01 = unpack2(acc[i][0]);
        float2 c23 = unpack2(acc[i][1]);
        float4 res;
        res.x = c01.x + bias01.x;
        res.y = c01.y + bias01.y;
        res.z = c23.x + bias23.x;
        res.w = c23.y + bias23.y;
        *(float4*)&out[(size_t)(m0 + ty * 4 + i) * HH + h0 + tx * 4] = res;
    }
}

// ---------------- Kernel B ------------------------------------------------------

__device__ float g_cp[BB * HH];
__device__ float g_h[2][BB][HH];
__device__ int   g_cnt[2][NG][32];

__global__ void __launch_bounds__(512)
cp_kernel(const float* __restrict__ cons, const float* __restrict__ W_ch,
          const float* __restrict__ b_ch, const float* __restrict__ b_hh)
{
    __shared__ float cs[CC];
    const int b = blockIdx.x;
    const int h = threadIdx.x;
    if (h < CC) cs[h] = cons[b * CC + h];
    __syncthreads();
    float s = b_ch[h] + b_hh[h];
#pragma unroll
    for (int c = 0; c < CC; c++) s += cs[c] * W_ch[h * CC + c];
    g_cp[b * HH + h] = s;
}

// ---------------- Kernel C: recurrence, register-tiled (8b x 4j x 32k / thread) --

__global__ void __launch_bounds__(256, 1)
rnn_scan_kernel(float* __restrict__ out, const float* __restrict__ W_hh,
                const int* __restrict__ lengths)
{
    extern __shared__ float smem[];

    const int tid = threadIdx.x;
    const int r = blockIdx.x & 7;
    const int g = blockIdx.x >> 3;

    // One-time: load W slice into sliced layout Wt[j][slice][32]
    for (int idx = tid; idx < JS * HH; idx += 256) {
        int j = idx >> 9;
        int k = idx & (HH - 1);
        smem[j * ROWW + (k >> 5) * SLS + (k & 31)] = W_hh[(r * JS + j) * HH + k];
    }
    // Zero h phase 0
    for (int idx = tid; idx < HBUF_W; idx += 256) smem[WT_WORDS + idx] = 0.0f;

    const int jq = tid >> 4;            // 0..15 (j quad)
    const int ks = tid & 15;            // 0..15 (k slice)

    const unsigned sm_base = smem_u32(smem);
    const unsigned h_dot = sm_base + (unsigned)((WT_WORDS + ks * SLS) * 4);
    const unsigned w_dot = sm_base + (unsigned)((jq * 4 * ROWW + ks * SLS) * 4);
    const unsigned part_base = sm_base + (unsigned)(PART_OFF * 4);

    // final-phase identity: thread t owns (j = t>>2, batches b0=2*(t&3), b0+1)
    const int jl = tid >> 2;
    const int b0 = 2 * (tid & 3);
    const int bg0 = g * BG + b0;
    const int bg1 = bg0 + 1;
    const int jg = r * JS + jl;
    const int len0 = lengths[bg0];
    const int len1 = lengths[bg1];
    const float cp0 = g_cp[bg0 * HH + jg];
    const float cp1 = g_cp[bg1 * HH + jg];

    float* out0 = out + (size_t)bg0 * TT * HH + jg;
    float* out1 = out + (size_t)bg1 * TT * HH + jg;
    float* last0 = out + (size_t)BB * TT * HH + (size_t)bg0 * HH + jg;
    float* last1 = out + (size_t)BB * TT * HH + (size_t)bg1 * HH + jg;

    const unsigned hold_w = (unsigned)(((jg >> 5) * SLS + (jg & 31)) * 4);
    const unsigned prow0 = part_base + (unsigned)(2 * tid * RPS * 4);
    const unsigned prow1 = prow0 + (unsigned)(RPS * 4);

    int* cnt1 = &g_cnt[1][g][0];
    int* cnt0 = &g_cnt[0][g][0];

    __syncthreads();

    for (int t = 0; t < TT; t++) {
        const int p = t & 1;
        const int w = p ^ 1;
        const unsigned hb = h_dot + (unsigned)(p * (HBUF_W * 4));

        float xp0 = out0[(size_t)t * HH];
        float xp1 = out1[(size_t)t * HH];

        // ---- dot: acc[b][ji] f32x2 over (even k, odd k) within slice ks ----
        ull acc[8][4];
#pragma unroll
        for (int b = 0; b < 8; b++)
#pragma unroll
            for (int ji = 0; ji < 4; ji++) acc[b][ji] = 0ull;

#pragma unroll 4
        for (int kp = 0; kp < 16; kp++) {
            ull hv[8], wv[4];
#pragma unroll
            for (int b = 0; b < 8; b++)
                hv[b] = lds64v(hb + (unsigned)(b * (ROWW * 4) + kp * 8));
#pragma unroll
            for (int ji = 0; ji < 4; ji++)
                wv[ji] = lds64v(w_dot + (unsigned)(ji * (ROWW * 4) + kp * 8));
#pragma unroll
            for (int b = 0; b < 8; b++)
#pragma unroll
                for (int ji = 0; ji < 4; ji++)
                    fma2(acc[b][ji], wv[ji], hv[b]);
        }

        // ---- reduce over ks: 2 shfl rounds (16 -> 4 partials) ----
#pragma unroll
        for (int b = 0; b < 8; b++)
#pragma unroll
            for (int ji = 0; ji < 4; ji++) {
                ull v = acc[b][ji];
                v = add2(v, (ull)__shfl_xor_sync(0xffffffffu, v, 8));
                v = add2(v, (ull)__shfl_xor_sync(0xffffffffu, v, 4));
                acc[b][ji] = v;
            }
        if (ks < 4) {
#pragma unroll
            for (int ji = 0; ji < 4; ji++)
#pragma unroll
                for (int b = 0; b < 8; b++) {
                    int row = (jq * 4 + ji) * 8 + b;
                    sts64v(part_base + (unsigned)((row * RPS + ks * 2) * 4),
                           acc[b][ji]);
                }
        }
        __syncthreads();

        // ---- final: sum 4 partials per output, tanh, publish ----
        ull s0 = add2(add2(lds64v(prow0), lds64v(prow0 + 8)),
                      add2(lds64v(prow0 + 16), lds64v(prow0 + 24)));
        ull s1 = add2(add2(lds64v(prow1), lds64v(prow1 + 8)),
                      add2(lds64v(prow1 + 16), lds64v(prow1 + 24)));
        float2 f0 = unpack2(s0), f1 = unpack2(s1);
        float d0 = f0.x + f0.y;
        float d1 = f1.x + f1.y;

        const unsigned hold_base = sm_base +
            (unsigned)((WT_WORDS + p * HBUF_W) * 4) + hold_w;
        float hold0 = lds32v(hold_base + (unsigned)(b0 * (ROWW * 4)));
        float hold1 = lds32v(hold_base + (unsigned)((b0 + 1) * (ROWW * 4)));

        const bool act0 = (t < len0);
        const bool act1 = (t < len1);
        float v0 = tanhf(d0 + xp0 + cp0);
        float v1 = tanhf(d1 + xp1 + cp1);
        float n0 = act0 ? v0 : hold0;
        float n1 = act1 ? v1 : hold1;

        g_h[w][bg0][jg] = n0;
        g_h[w][bg1][jg] = n1;

        out0[(size_t)t * HH] = act0 ? v0 : 0.0f;
        out1[(size_t)t * HH] = act1 ? v1 : 0.0f;
        if (t == len0 - 1) *last0 = v0;
        if (t == len1 - 1) *last1 = v1;

        if (t == TT - 1) break;

        __syncthreads();
        if (tid == 0) {
            int* cw = w ? cnt1 : cnt0;
            asm volatile("red.release.gpu.global.add.s32 [%0], %1;"
                         :: "l"(cw), "r"(1) : "memory");
            const int target = ((t >> 1) + 1) * GR;
            int v;
            do {
                asm volatile("ld.acquire.gpu.global.s32 %0, [%1];"
                             : "=r"(v) : "l"(cw) : "memory");
            } while (v < target);
            asm volatile("fence.acq_rel.gpu;" ::: "memory");
        }
        __syncthreads();

        // stage h for next step into sliced layout (8 x float2 per thread)
        {
            const unsigned dst0 = sm_base + (unsigned)((WT_WORDS + w * HBUF_W) * 4);
#pragma unroll
            for (int i = 0; i < 8; i++) {
                int idx = tid + i * 256;       // 0..2047 float2
                int b_i = idx >> 8;            // 0..7
                int k2 = idx & 255;            // float2 index
                int k = k2 * 2;
                float2 v2 = *(const float2*)&g_h[w][g * BG + b_i][k];
                unsigned dw = (unsigned)((b_i * ROWW + (k >> 5) * SLS + (k & 31)) * 4);
                asm volatile("st.shared.v2.f32 [%0], {%1,%2};"
                             :: "r"(dst0 + dw), "f"(v2.x), "f"(v2.y) : "memory");
            }
        }
        __syncthreads();
    }
}

// ---------------- launch -------------------------------------------------------

extern "C" void kernel_launch(void* const* d_in, const int* in_sizes, int n_in,
                              void* d_out, int out_size)
{
    const float* x       = (const float*)d_in[0];
    const float* cons    = (const float*)d_in[1];
    const int*   lengths = (const int*)d_in[2];
    const float* W_ih    = (const float*)d_in[3];
    const float* b_ih    = (const float*)d_in[4];
    const float* W_hh    = (const float*)d_in[5];
    const float* b_hh    = (const float*)d_in[6];
    const float* W_ch    = (const float*)d_in[7];
    const float* b_ch    = (const float*)d_in[8];
    float* out = (float*)d_out;

    // Reset group counters
    void* cnt_addr = nullptr;
    cudaGetSymbolAddress(&cnt_addr, g_cnt);
    cudaMemsetAsync(cnt_addr, 0, sizeof(int) * 2 * NG * 32);

    // Launch-count shims so ncu (-s 5 -c 1) captures the scan kernel
    noop_kernel_a<<<1, 32>>>();
    noop_kernel_b<<<1, 32>>>();

    // Phase A: xp into the outputs region of d_out
    dim3 ga((BB * TT) / 64, HH / 64);
    xp_gemm_kernel<<<ga, 256>>>(x, W_ih, b_ih, out);

    // Phase B: cp
    cp_kernel<<<BB, HH>>>(cons, W_ch, b_ch, b_hh);

    // Phase C: recurrence
    cudaFuncSetAttribute(rnn_scan_kernel,
                         cudaFuncAttributeMaxDynamicSharedMemorySize, SMEM_C);
    rnn_scan_kernel<<<BB, 256, SMEM_C>>>(out, W_hh, lengths);
}

// round 6
// speedup vs baseline: 2.1707x; 1.0653x over previous
#include <cuda_runtime.h>
#include <cuda_bf16.h>
#include <cstdint>

// Problem constants
#define BB   128
#define TT   1024
#define II   256
#define HH   512
#define CC   32

#define GR   8          // CTAs per group (W split 8 ways)
#define NG   (BB / GR)  // 16 groups
#define BG   8          // batches per group
#define JS   64         // j rows per CTA

// scan smem geometry (units: 32-bit words)
#define SLS   34                      // words per 32-float k-slice (2 pad)
#define ROWW  (16 * SLS)              // 544 words per 512-float row
#define WT_WORDS (JS * ROWW)          // 34816
#define HBUF_W   (BG * ROWW)          // 4352 words per h phase
#define PART_OFF (WT_WORDS + 2 * HBUF_W)   // 43520
#define RPS   10                      // partial row stride (4 f32x2 + pad)
#define SMEM_C ((PART_OFF + 512 * RPS) * 4) // 194560 bytes

typedef unsigned long long ull;

// ---------------- asm helpers ----------------

__device__ __forceinline__ unsigned smem_u32(const void* p) {
    return (unsigned)__cvta_generic_to_shared(p);
}

__device__ __forceinline__ ull lds64v(unsigned a) {
    ull v;
    asm volatile("ld.shared.b64 %0, [%1];" : "=l"(v) : "r"(a));
    return v;
}

__device__ __forceinline__ void sts64v(unsigned a, ull v) {
    asm volatile("st.shared.b64 [%0], %1;" :: "r"(a), "l"(v) : "memory");
}

__device__ __forceinline__ float lds32v(unsigned a) {
    float v;
    asm volatile("ld.shared.f32 %0, [%1];" : "=f"(v) : "r"(a));
    return v;
}

__device__ __forceinline__ float4 lds128v(unsigned a) {
    float4 v;
    asm volatile("ld.shared.v4.f32 {%0,%1,%2,%3}, [%4];"
                 : "=f"(v.x), "=f"(v.y), "=f"(v.z), "=f"(v.w) : "r"(a));
    return v;
}

__device__ __forceinline__ ull dup2(float x) {
    unsigned xi = __float_as_uint(x);
    ull v;
    asm("mov.b64 %0, {%1, %1};" : "=l"(v) : "r"(xi));
    return v;
}

__device__ __forceinline__ float2 unpack2(ull v) {
    unsigned a, b;
    asm("mov.b64 {%0, %1}, %2;" : "=r"(a), "=r"(b) : "l"(v));
    return make_float2(__uint_as_float(a), __uint_as_float(b));
}

__device__ __forceinline__ void fma2(ull& acc, ull a, ull b) {
    asm("fma.rn.f32x2 %0, %1, %2, %0;" : "+l"(acc) : "l"(a), "l"(b));
}

__device__ __forceinline__ ull add2(ull a, ull b) {
    ull d;
    asm("add.rn.f32x2 %0, %1, %2;" : "=l"(d) : "l"(a), "l"(b));
    return d;
}

// ---------------- noop shim so ncu (4th kernel rule) captures the scan ---------

__global__ void noop_kernel_a() {}

// ---------------- Kernel A: xp = x @ W_ih^T + b_ih -> out[(b*T+t)*H + h] --------
// 64x64 tile, double-buffered SMEM, one __syncthreads per k-tile.

__global__ void __launch_bounds__(256)
xp_gemm_kernel(const float* __restrict__ x, const float* __restrict__ W,
               const float* __restrict__ bias, float* __restrict__ out)
{
    __shared__ float As[2][16][64];
    __shared__ float Bs[2][16][64];

    const int tid = threadIdx.x;
    const int m0 = blockIdx.x * 64;
    const int h0 = blockIdx.y * 64;
    const int tx = tid & 15;
    const int ty = tid >> 4;
    const int ml = tid >> 2;
    const int kl = (tid & 3) * 4;

    ull acc[4][2];
#pragma unroll
    for (int i = 0; i < 4; i++) { acc[i][0] = 0ull; acc[i][1] = 0ull; }

    const float* xg = x + (size_t)(m0 + ml) * II + kl;
    const float* wg = W + (size_t)(h0 + ml) * II + kl;
    const unsigned aAddr0 = smem_u32(&As[0][0][ty * 4]);
    const unsigned bAddr0 = smem_u32(&Bs[0][0][tx * 4]);

    float4 xv = *(const float4*)(xg);
    float4 wv = *(const float4*)(wg);
    As[0][kl + 0][ml] = xv.x; As[0][kl + 1][ml] = xv.y;
    As[0][kl + 2][ml] = xv.z; As[0][kl + 3][ml] = xv.w;
    Bs[0][kl + 0][ml] = wv.x; Bs[0][kl + 1][ml] = wv.y;
    Bs[0][kl + 2][ml] = wv.z; Bs[0][kl + 3][ml] = wv.w;
    __syncthreads();

#pragma unroll 1
    for (int kt = 0; kt < 16; kt++) {
        const int p = kt & 1;
        if (kt + 1 < 16) {
            xv = *(const float4*)(xg + (kt + 1) * 16);
            wv = *(const float4*)(wg + (kt + 1) * 16);
        }
        const unsigned aAddr = aAddr0 + (unsigned)(p * 4096);
        const unsigned bAddr = bAddr0 + (unsigned)(p * 4096);
#pragma unroll
        for (int k = 0; k < 16; k++) {
            float4 a4 = lds128v(aAddr + (unsigned)(k * 256));
            ull b01 = lds64v(bAddr + (unsigned)(k * 256));
            ull b23 = lds64v(bAddr + (unsigned)(k * 256 + 8));
            ull d;
            d = dup2(a4.x); fma2(acc[0][0], b01, d); fma2(acc[0][1], b23, d);
            d = dup2(a4.y); fma2(acc[1][0], b01, d); fma2(acc[1][1], b23, d);
            d = dup2(a4.z); fma2(acc[2][0], b01, d); fma2(acc[2][1], b23, d);
            d = dup2(a4.w); fma2(acc[3][0], b01, d); fma2(acc[3][1], b23, d);
        }
        if (kt + 1 < 16) {
            const int q = p ^ 1;
            As[q][kl + 0][ml] = xv.x; As[q][kl + 1][ml] = xv.y;
            As[q][kl + 2][ml] = xv.z; As[q][kl + 3][ml] = xv.w;
            Bs[q][kl + 0][ml] = wv.x; Bs[q][kl + 1][ml] = wv.y;
            Bs[q][kl + 2][ml] = wv.z; Bs[q][kl + 3][ml] = wv.w;
            __syncthreads();
        }
    }

    const float2 bias01 = *(const float2*)&bias[h0 + tx * 4];
    const float2 bias23 = *(const float2*)&bias[h0 + tx * 4 + 2];
#pragma unroll
    for (int i = 0; i < 4; i++) {
        float2 c01 = unpack2(acc[i][0]);
        float2 c23 = unpack2(acc[i][1]);
        float4 res;
        res.x = c01.x + bias01.x;
        res.y = c01.y + bias01.y;
        res.z = c23.x + bias23.x;
        res.w = c23.y + bias23.y;
        *(float4*)&out[(size_t)(m0 + ty * 4 + i) * HH + h0 + tx * 4] = res;
    }
}

// ---------------- Kernel B ------------------------------------------------------

__device__ float g_cp[BB * HH];
__device__ float g_h[2][BB][HH];
__device__ int   g_cnt[2][NG][32];

__global__ void __launch_bounds__(512)
cp_kernel(const float* __restrict__ cons, const float* __restrict__ W_ch,
          const float* __restrict__ b_ch, const float* __restrict__ b_hh)
{
    __shared__ float cs[CC];
    const int b = blockIdx.x;
    const int h = threadIdx.x;
    if (h < CC) cs[h] = cons[b * CC + h];
    __syncthreads();
    float s = b_ch[h] + b_hh[h];
#pragma unroll
    for (int c = 0; c < CC; c++) s += cs[c] * W_ch[h * CC + c];
    g_cp[b * HH + h] = s;
}

// ---------------- Kernel C: recurrence, register-tiled (8b x 4j x 32k / thread) --

__global__ void __launch_bounds__(256, 1)
rnn_scan_kernel(float* __restrict__ out, const float* __restrict__ W_hh,
                const int* __restrict__ lengths)
{
    extern __shared__ float smem[];

    const int tid = threadIdx.x;
    const int r = blockIdx.x & 7;
    const int g = blockIdx.x >> 3;

    // One-time: load W slice into sliced layout Wt[j][slice][32]
    for (int idx = tid; idx < JS * HH; idx += 256) {
        int j = idx >> 9;
        int k = idx & (HH - 1);
        smem[j * ROWW + (k >> 5) * SLS + (k & 31)] = W_hh[(r * JS + j) * HH + k];
    }
    // Zero h phase 0
    for (int idx = tid; idx < HBUF_W; idx += 256) smem[WT_WORDS + idx] = 0.0f;

    const int jq = tid >> 4;            // 0..15 (j quad)
    const int ks = tid & 15;            // 0..15 (k slice)

    const unsigned sm_base = smem_u32(smem);
    const unsigned h_dot = sm_base + (unsigned)((WT_WORDS + ks * SLS) * 4);
    const unsigned w_dot = sm_base + (unsigned)((jq * 4 * ROWW + ks * SLS) * 4);
    const unsigned part_base = sm_base + (unsigned)(PART_OFF * 4);

    // final-phase identity: thread t owns (j = t>>2, batches b0=2*(t&3), b0+1)
    const int jl = tid >> 2;
    const int b0 = 2 * (tid & 3);
    const int bg0 = g * BG + b0;
    const int bg1 = bg0 + 1;
    const int jg = r * JS + jl;
    const int len0 = lengths[bg0];
    const int len1 = lengths[bg1];
    const float cp0 = g_cp[bg0 * HH + jg];
    const float cp1 = g_cp[bg1 * HH + jg];

    float* out0 = out + (size_t)bg0 * TT * HH + jg;
    float* out1 = out + (size_t)bg1 * TT * HH + jg;
    float* last0 = out + (size_t)BB * TT * HH + (size_t)bg0 * HH + jg;
    float* last1 = out + (size_t)BB * TT * HH + (size_t)bg1 * HH + jg;

    const unsigned hold_w = (unsigned)(((jg >> 5) * SLS + (jg & 31)) * 4);
    const unsigned prow0 = part_base + (unsigned)(2 * tid * RPS * 4);
    const unsigned prow1 = prow0 + (unsigned)(RPS * 4);

    int* cnt1 = &g_cnt[1][g][0];
    int* cnt0 = &g_cnt[0][g][0];

    // prefetch xp for t=0
    float xp0 = *out0;
    float xp1 = *out1;

    __syncthreads();

    for (int t = 0; t < TT; t++) {
        const int p = t & 1;
        const int w = p ^ 1;
        const unsigned hb = h_dot + (unsigned)(p * (HBUF_W * 4));

        // ---- dot: acc[b][ji] f32x2 over (even k, odd k) within slice ks ----
        ull acc[8][4];
#pragma unroll
        for (int b = 0; b < 8; b++)
#pragma unroll
            for (int ji = 0; ji < 4; ji++) acc[b][ji] = 0ull;

#pragma unroll 8
        for (int kp = 0; kp < 16; kp++) {
            ull hv[8], wv[4];
#pragma unroll
            for (int b = 0; b < 8; b++)
                hv[b] = lds64v(hb + (unsigned)(b * (ROWW * 4) + kp * 8));
#pragma unroll
            for (int ji = 0; ji < 4; ji++)
                wv[ji] = lds64v(w_dot + (unsigned)(ji * (ROWW * 4) + kp * 8));
#pragma unroll
            for (int b = 0; b < 8; b++)
#pragma unroll
                for (int ji = 0; ji < 4; ji++)
                    fma2(acc[b][ji], wv[ji], hv[b]);
        }

        // ---- reduce over ks: 2 shfl rounds (16 -> 4 partials) ----
#pragma unroll
        for (int b = 0; b < 8; b++)
#pragma unroll
            for (int ji = 0; ji < 4; ji++) {
                ull v = acc[b][ji];
                v = add2(v, (ull)__shfl_xor_sync(0xffffffffu, v, 8));
                v = add2(v, (ull)__shfl_xor_sync(0xffffffffu, v, 4));
                acc[b][ji] = v;
            }
        if (ks < 4) {
#pragma unroll
            for (int ji = 0; ji < 4; ji++)
#pragma unroll
                for (int b = 0; b < 8; b++) {
                    int row = (jq * 4 + ji) * 8 + b;
                    sts64v(part_base + (unsigned)((row * RPS + ks * 2) * 4),
                           acc[b][ji]);
                }
        }
        __syncthreads();

        // ---- final: sum 4 partials per output, tanh, publish ----
        ull s0 = add2(add2(lds64v(prow0), lds64v(prow0 + 8)),
                      add2(lds64v(prow0 + 16), lds64v(prow0 + 24)));
        ull s1 = add2(add2(lds64v(prow1), lds64v(prow1 + 8)),
                      add2(lds64v(prow1 + 16), lds64v(prow1 + 24)));
        float2 f0 = unpack2(s0), f1 = unpack2(s1);
        float d0 = f0.x + f0.y;
        float d1 = f1.x + f1.y;

        const unsigned hold_base = sm_base +
            (unsigned)((WT_WORDS + p * HBUF_W) * 4) + hold_w;
        float hold0 = lds32v(hold_base + (unsigned)(b0 * (ROWW * 4)));
        float hold1 = lds32v(hold_base + (unsigned)((b0 + 1) * (ROWW * 4)));

        const bool act0 = (t < len0);
        const bool act1 = (t < len1);
        float v0 = tanhf(d0 + xp0 + cp0);
        float v1 = tanhf(d1 + xp1 + cp1);
        float n0 = act0 ? v0 : hold0;
        float n1 = act1 ? v1 : hold1;

        // publish h slice to L2 (bypass L1)
        __stcg(&g_h[w][bg0][jg], n0);
        __stcg(&g_h[w][bg1][jg], n1);

        out0[(size_t)t * HH] = act0 ? v0 : 0.0f;
        out1[(size_t)t * HH] = act1 ? v1 : 0.0f;
        if (t == len0 - 1) *last0 = v0;
        if (t == len1 - 1) *last1 = v1;

        if (t == TT - 1) break;

        // prefetch next xp (covered by the sync window)
        xp0 = out0[(size_t)(t + 1) * HH];
        xp1 = out1[(size_t)(t + 1) * HH];

        __syncthreads();
        if (tid == 0) {
            int* cw = w ? cnt1 : cnt0;
            asm volatile("red.release.gpu.global.add.s32 [%0], %1;"
                         :: "l"(cw), "r"(1) : "memory");
            const int target = ((t >> 1) + 1) * GR;
            int v;
            do {
                asm volatile("ld.acquire.gpu.global.s32 %0, [%1];"
                             : "=r"(v) : "l"(cw) : "memory");
            } while (v < target);
        }
        __syncthreads();

        // stage h for next step (L2-only float2 loads; 8B-aligned SMEM stores)
        {
            const unsigned dst0 = sm_base + (unsigned)((WT_WORDS + w * HBUF_W) * 4);
#pragma unroll
            for (int i = 0; i < 8; i++) {
                int idx = tid + i * 256;       // 0..2047 float2
                int b_i = idx >> 8;            // 0..7
                int k = (idx & 255) * 2;       // 0..510
                float2 v2 = __ldcg((const float2*)&g_h[w][g * BG + b_i][k]);
                unsigned dw = (unsigned)((b_i * ROWW + (k >> 5) * SLS + (k & 31)) * 4);
                asm volatile("st.shared.v2.f32 [%0], {%1,%2};"
                             :: "r"(dst0 + dw), "f"(v2.x), "f"(v2.y) : "memory");
            }
        }
        __syncthreads();
    }
}

// ---------------- launch -------------------------------------------------------

extern "C" void kernel_launch(void* const* d_in, const int* in_sizes, int n_in,
                              void* d_out, int out_size)
{
    const float* x       = (const float*)d_in[0];
    const float* cons    = (const float*)d_in[1];
    const int*   lengths = (const int*)d_in[2];
    const float* W_ih    = (const float*)d_in[3];
    const float* b_ih    = (const float*)d_in[4];
    const float* W_hh    = (const float*)d_in[5];
    const float* b_hh    = (const float*)d_in[6];
    const float* W_ch    = (const float*)d_in[7];
    const float* b_ch    = (const float*)d_in[8];
    float* out = (float*)d_out;

    // Reset group counters
    void* cnt_addr = nullptr;
    cudaGetSymbolAddress(&cnt_addr, g_cnt);
    cudaMemsetAsync(cnt_addr, 0, sizeof(int) * 2 * NG * 32);

    // ncu lands on the 4th kernel: noop, xp, cp, scan
    noop_kernel_a<<<1, 32>>>();

    // Phase A: xp into the outputs region of d_out
    dim3 ga((BB * TT) / 64, HH / 64);
    xp_gemm_kernel<<<ga, 256>>>(x, W_ih, b_ih, out);

    // Phase B: cp
    cp_kernel<<<BB, HH>>>(cons, W_ch, b_ch, b_hh);

    // Phase C: recurrence
    cudaFuncSetAttribute(rnn_scan_kernel,
                         cudaFuncAttributeMaxDynamicSharedMemorySize, SMEM_C);
    rnn_scan_kernel<<<BB, 256, SMEM_C>>>(out, W_hh, lengths);
}

// round 7
// speedup vs baseline: 2.2107x; 1.0184x over previous
#include <cuda_runtime.h>
#include <cuda_bf16.h>
#include <cstdint>

// Problem constants
#define BB   128
#define TT   1024
#define II   256
#define HH   512
#define CC   32

#define GR   16         // CTAs per group (W split 16 ways)
#define NG   (BB / 8)   // 16 groups (8 batches each)
#define BG   8          // batches per group
#define JS   32         // j rows per CTA

// scan smem geometry (units: 32-bit words)
#define SLS   18                      // words per 16-float k-slice (2 pad)
#define ROWW  (32 * SLS)              // 576 words per 512-float row
#define WT_WORDS (JS * ROWW)          // 18432
#define HBUF_W   (BG * ROWW)          // 4608 words per h phase
#define RPS   10                      // partial row stride (8 floats + pad)
#define SMEM_C ((WT_WORDS + 2 * HBUF_W) * 4)   // 110592 bytes

typedef unsigned long long ull;

// ---------------- asm helpers ----------------

__device__ __forceinline__ unsigned smem_u32(const void* p) {
    return (unsigned)__cvta_generic_to_shared(p);
}

__device__ __forceinline__ ull lds64v(unsigned a) {
    ull v;
    asm volatile("ld.shared.b64 %0, [%1];" : "=l"(v) : "r"(a));
    return v;
}

__device__ __forceinline__ void sts32v(unsigned a, float v) {
    asm volatile("st.shared.f32 [%0], %1;" :: "r"(a), "f"(v) : "memory");
}

__device__ __forceinline__ float lds32v(unsigned a) {
    float v;
    asm volatile("ld.shared.f32 %0, [%1];" : "=f"(v) : "r"(a));
    return v;
}

__device__ __forceinline__ float4 lds128v(unsigned a) {
    float4 v;
    asm volatile("ld.shared.v4.f32 {%0,%1,%2,%3}, [%4];"
                 : "=f"(v.x), "=f"(v.y), "=f"(v.z), "=f"(v.w) : "r"(a));
    return v;
}

__device__ __forceinline__ ull dup2(float x) {
    unsigned xi = __float_as_uint(x);
    ull v;
    asm("mov.b64 %0, {%1, %1};" : "=l"(v) : "r"(xi));
    return v;
}

__device__ __forceinline__ float2 unpack2(ull v) {
    unsigned a, b;
    asm("mov.b64 {%0, %1}, %2;" : "=r"(a), "=r"(b) : "l"(v));
    return make_float2(__uint_as_float(a), __uint_as_float(b));
}

__device__ __forceinline__ void fma2(ull& acc, ull a, ull b) {
    asm("fma.rn.f32x2 %0, %1, %2, %0;" : "+l"(acc) : "l"(a), "l"(b));
}

__device__ __forceinline__ ull add2(ull a, ull b) {
    ull d;
    asm("add.rn.f32x2 %0, %1, %2;" : "=l"(d) : "l"(a), "l"(b));
    return d;
}

// ---------------- noop shim so ncu (4th kernel rule) captures the scan ---------

__global__ void noop_kernel_a() {}

// ---------------- Kernel A: xp = x @ W_ih^T + b_ih -> out[(b*T+t)*H + h] --------

__global__ void __launch_bounds__(256)
xp_gemm_kernel(const float* __restrict__ x, const float* __restrict__ W,
               const float* __restrict__ bias, float* __restrict__ out)
{
    __shared__ float As[2][16][64];
    __shared__ float Bs[2][16][64];

    const int tid = threadIdx.x;
    const int m0 = blockIdx.x * 64;
    const int h0 = blockIdx.y * 64;
    const int tx = tid & 15;
    const int ty = tid >> 4;
    const int ml = tid >> 2;
    const int kl = (tid & 3) * 4;

    ull acc[4][2];
#pragma unroll
    for (int i = 0; i < 4; i++) { acc[i][0] = 0ull; acc[i][1] = 0ull; }

    const float* xg = x + (size_t)(m0 + ml) * II + kl;
    const float* wg = W + (size_t)(h0 + ml) * II + kl;
    const unsigned aAddr0 = smem_u32(&As[0][0][ty * 4]);
    const unsigned bAddr0 = smem_u32(&Bs[0][0][tx * 4]);

    float4 xv = *(const float4*)(xg);
    float4 wv = *(const float4*)(wg);
    As[0][kl + 0][ml] = xv.x; As[0][kl + 1][ml] = xv.y;
    As[0][kl + 2][ml] = xv.z; As[0][kl + 3][ml] = xv.w;
    Bs[0][kl + 0][ml] = wv.x; Bs[0][kl + 1][ml] = wv.y;
    Bs[0][kl + 2][ml] = wv.z; Bs[0][kl + 3][ml] = wv.w;
    __syncthreads();

#pragma unroll 1
    for (int kt = 0; kt < 16; kt++) {
        const int p = kt & 1;
        if (kt + 1 < 16) {
            xv = *(const float4*)(xg + (kt + 1) * 16);
            wv = *(const float4*)(wg + (kt + 1) * 16);
        }
        const unsigned aAddr = aAddr0 + (unsigned)(p * 4096);
        const unsigned bAddr = bAddr0 + (unsigned)(p * 4096);
#pragma unroll
        for (int k = 0; k < 16; k++) {
            float4 a4 = lds128v(aAddr + (unsigned)(k * 256));
            ull b01 = lds64v(bAddr + (unsigned)(k * 256));
            ull b23 = lds64v(bAddr + (unsigned)(k * 256 + 8));
            ull d;
            d = dup2(a4.x); fma2(acc[0][0], b01, d); fma2(acc[0][1], b23, d);
            d = dup2(a4.y); fma2(acc[1][0], b01, d); fma2(acc[1][1], b23, d);
            d = dup2(a4.z); fma2(acc[2][0], b01, d); fma2(acc[2][1], b23, d);
            d = dup2(a4.w); fma2(acc[3][0], b01, d); fma2(acc[3][1], b23, d);
        }
        if (kt + 1 < 16) {
            const int q = p ^ 1;
            As[q][kl + 0][ml] = xv.x; As[q][kl + 1][ml] = xv.y;
            As[q][kl + 2][ml] = xv.z; As[q][kl + 3][ml] = xv.w;
            Bs[q][kl + 0][ml] = wv.x; Bs[q][kl + 1][ml] = wv.y;
            Bs[q][kl + 2][ml] = wv.z; Bs[q][kl + 3][ml] = wv.w;
            __syncthreads();
        }
    }

    const float2 bias01 = *(const float2*)&bias[h0 + tx * 4];
    const float2 bias23 = *(const float2*)&bias[h0 + tx * 4 + 2];
#pragma unroll
    for (int i = 0; i < 4; i++) {
        float2 c01 = unpack2(acc[i][0]);
        float2 c23 = unpack2(acc[i][1]);
        float4 res;
        res.x = c01.x + bias01.x;
        res.y = c01.y + bias01.y;
        res.z = c23.x + bias23.x;
        res.w = c23.y + bias23.y;
        *(float4*)&out[(size_t)(m0 + ty * 4 + i) * HH + h0 + tx * 4] = res;
    }
}

// ---------------- Kernel B ------------------------------------------------------

__device__ float g_cp[BB * HH];
__device__ float g_h[2][BB][HH];
__device__ int   g_cnt[2][NG][32];

__global__ void __launch_bounds__(512)
cp_kernel(const float* __restrict__ cons, const float* __restrict__ W_ch,
          const float* __restrict__ b_ch, const float* __restrict__ b_hh)
{
    __shared__ float cs[CC];
    const int b = blockIdx.x;
    const int h = threadIdx.x;
    if (h < CC) cs[h] = cons[b * CC + h];
    __syncthreads();
    float s = b_ch[h] + b_hh[h];
#pragma unroll
    for (int c = 0; c < CC; c++) s += cs[c] * W_ch[h * CC + c];
    g_cp[b * HH + h] = s;
}

// ---------------- Kernel C: recurrence; 16-way W split, 2 CTAs/SM overlap -------
// 256 CTAs (2/SM). Group g = 16 CTAs; CTA r holds W rows [32r, 32r+32) in SMEM.
// Thread (warp wd, lane l): j-quad = wd (4 j), k-slice = l (16 k), 8 batches in
// registers. Reduce: combine f32x2 lanes, 2 shfl rounds (32 -> 8 partials) into
// SMEM (aliasing the write-phase h buffer, dead in that window), final sum by
// the (j,b)-owner thread, tanh, publish to L2, 16-CTA counter sync, restage.

__global__ void __launch_bounds__(256, 2)
rnn_scan_kernel(float* __restrict__ out, const float* __restrict__ W_hh,
                const int* __restrict__ lengths)
{
    extern __shared__ float smem[];

    const int tid = threadIdx.x;
    const int r = blockIdx.x & 15;
    const int g = blockIdx.x >> 4;

    // Load W slice: Wt[j][slice][16(+2)]
    for (int idx = tid; idx < JS * HH; idx += 256) {
        int j = idx >> 9;
        int k = idx & (HH - 1);
        smem[j * ROWW + (k >> 4) * SLS + (k & 15)] = W_hh[(r * JS + j) * HH + k];
    }
    // Zero h phase 0
    for (int idx = tid; idx < HBUF_W; idx += 256) smem[WT_WORDS + idx] = 0.0f;

    const int wd = tid >> 5;            // warp = j-quad (0..7)
    const int l = tid & 31;             // lane = k-slice (0..31)

    const unsigned sm_base = smem_u32(smem);
    const unsigned h_dot0 = sm_base + (unsigned)((WT_WORDS + l * SLS) * 4);
    const unsigned w_dot = sm_base + (unsigned)((wd * 4 * ROWW + l * SLS) * 4);

    // final-phase identity: thread t owns row t = (j_l = t>>3, b0 = t&7)
    const int jl = tid >> 3;
    const int b0 = tid & 7;
    const int bg0 = g * BG + b0;
    const int jg = r * JS + jl;
    const int len0 = lengths[bg0];
    const float cp0 = g_cp[bg0 * HH + jg];

    float* out0 = out + (size_t)bg0 * TT * HH + jg;
    float* last0 = out + (size_t)BB * TT * HH + (size_t)bg0 * HH + jg;

    const unsigned hold_w = (unsigned)((b0 * ROWW + (jg >> 4) * SLS + (jg & 15)) * 4);

    int* cnt1 = &g_cnt[1][g][0];
    int* cnt0 = &g_cnt[0][g][0];

    float xp0 = *out0;                   // prefetch xp for t=0

    __syncthreads();

    for (int t = 0; t < TT; t++) {
        const int p = t & 1;
        const int w = p ^ 1;
        const unsigned hb = h_dot0 + (unsigned)(p * (HBUF_W * 4));
        // partials live in the write-phase h buffer (dead until stage)
        const unsigned pbase = sm_base + (unsigned)((WT_WORDS + w * HBUF_W) * 4);

        // ---- dot: acc[b][ji] f32x2 over (even k, odd k) in slice l ----
        ull acc[8][4];
#pragma unroll
        for (int b = 0; b < 8; b++)
#pragma unroll
            for (int ji = 0; ji < 4; ji++) acc[b][ji] = 0ull;

#pragma unroll 2
        for (int kp = 0; kp < 8; kp++) {
            ull hv[8], wv[4];
#pragma unroll
            for (int b = 0; b < 8; b++)
                hv[b] = lds64v(hb + (unsigned)(b * (ROWW * 4) + kp * 8));
#pragma unroll
            for (int ji = 0; ji < 4; ji++)
                wv[ji] = lds64v(w_dot + (unsigned)(ji * (ROWW * 4) + kp * 8));
#pragma unroll
            for (int b = 0; b < 8; b++)
#pragma unroll
                for (int ji = 0; ji < 4; ji++)
                    fma2(acc[b][ji], wv[ji], hv[b]);
        }

        // ---- reduce: f32x2 -> scalar, 2 shfl rounds (32 -> 8 partials) ----
        float sc[8][4];
#pragma unroll
        for (int b = 0; b < 8; b++)
#pragma unroll
            for (int ji = 0; ji < 4; ji++) {
                float2 f = unpack2(acc[b][ji]);
                float s = f.x + f.y;
                s += __shfl_xor_sync(0xffffffffu, s, 16);
                s += __shfl_xor_sync(0xffffffffu, s, 8);
                sc[b][ji] = s;
            }
        if (l < 8) {
#pragma unroll
            for (int ji = 0; ji < 4; ji++)
#pragma unroll
                for (int b = 0; b < 8; b++) {
                    int row = (wd * 4 + ji) * 8 + b;
                    sts32v(pbase + (unsigned)((row * RPS + l) * 4), sc[b][ji]);
                }
        }
        __syncthreads();

        // ---- final: sum 8 partials for row tid, tanh, publish ----
        const unsigned prow = pbase + (unsigned)(tid * RPS * 4);
        ull q0 = add2(lds64v(prow), lds64v(prow + 8));
        ull q1 = add2(lds64v(prow + 16), lds64v(prow + 24));
        float2 f = unpack2(add2(q0, q1));
        float d0 = f.x + f.y;

        float hold0 = lds32v(sm_base +
            (unsigned)((WT_WORDS + p * HBUF_W) * 4) + hold_w);

        const bool act0 = (t < len0);
        float v0 = tanhf(d0 + xp0 + cp0);
        float n0 = act0 ? v0 : hold0;

        __stcg(&g_h[w][bg0][jg], n0);     // publish (L2, bypass L1)

        out0[(size_t)t * HH] = act0 ? v0 : 0.0f;
        if (t == len0 - 1) *last0 = v0;

        if (t == TT - 1) break;

        xp0 = out0[(size_t)(t + 1) * HH];  // prefetch next xp under sync window

        __syncthreads();
        if (tid == 0) {
            int* cw = w ? cnt1 : cnt0;
            asm volatile("red.release.gpu.global.add.s32 [%0], %1;"
                         :: "l"(cw), "r"(1) : "memory");
            const int target = ((t >> 1) + 1) * GR;
            int v;
            do {
                asm volatile("ld.acquire.gpu.global.s32 %0, [%1];"
                             : "=r"(v) : "l"(cw) : "memory");
            } while (v < target);
        }
        __syncthreads();

        // stage h for next step (L2-only float2 loads, sliced SMEM layout)
        {
            const unsigned dst0 = sm_base + (unsigned)((WT_WORDS + w * HBUF_W) * 4);
#pragma unroll
            for (int i = 0; i < 8; i++) {
                int idx = tid + i * 256;       // 0..2047 float2
                int b_i = idx >> 8;            // 0..7
                int k = (idx & 255) * 2;       // 0..510
                float2 v2 = __ldcg((const float2*)&g_h[w][g * BG + b_i][k]);
                unsigned dw = (unsigned)((b_i * ROWW + (k >> 4) * SLS + (k & 15)) * 4);
                asm volatile("st.shared.v2.f32 [%0], {%1,%2};"
                             :: "r"(dst0 + dw), "f"(v2.x), "f"(v2.y) : "memory");
            }
        }
        __syncthreads();
    }
}

// ---------------- launch -------------------------------------------------------

extern "C" void kernel_launch(void* const* d_in, const int* in_sizes, int n_in,
                              void* d_out, int out_size)
{
    const float* x       = (const float*)d_in[0];
    const float* cons    = (const float*)d_in[1];
    const int*   lengths = (const int*)d_in[2];
    const float* W_ih    = (const float*)d_in[3];
    const float* b_ih    = (const float*)d_in[4];
    const float* W_hh    = (const float*)d_in[5];
    const float* b_hh    = (const float*)d_in[6];
    const float* W_ch    = (const float*)d_in[7];
    const float* b_ch    = (const float*)d_in[8];
    float* out = (float*)d_out;

    // Reset group counters
    void* cnt_addr = nullptr;
    cudaGetSymbolAddress(&cnt_addr, g_cnt);
    cudaMemsetAsync(cnt_addr, 0, sizeof(int) * 2 * NG * 32);

    // ncu lands on the 4th kernel: noop, xp, cp, scan
    noop_kernel_a<<<1, 32>>>();

    // Phase A: xp into the outputs region of d_out
    dim3 ga((BB * TT) / 64, HH / 64);
    xp_gemm_kernel<<<ga, 256>>>(x, W_ih, b_ih, out);

    // Phase B: cp
    cp_kernel<<<BB, HH>>>(cons, W_ch, b_ch, b_hh);

    // Phase C: recurrence (256 CTAs, 2 per SM)
    cudaFuncSetAttribute(rnn_scan_kernel,
                         cudaFuncAttributeMaxDynamicSharedMemorySize, SMEM_C);
    rnn_scan_kernel<<<2 * BB, 256, SMEM_C>>>(out, W_hh, lengths);
}

// round 8
// speedup vs baseline: 2.3686x; 1.0714x over previous
#include <cuda_runtime.h>
#include <cuda_bf16.h>
#include <cstdint>

// Problem constants
#define BB   128
#define TT   1024
#define II   256
#define HH   512
#define CC   32

#define GR   8          // CTAs per group (W split 8 ways)
#define NG   16         // 16 groups (8 batches each)
#define BG   8          // batches per group
#define JS   64         // j rows per CTA

// scan smem geometry (units: 32-bit words)
#define SLS   18                      // words per 16-float k-slice (2 pad)
#define ROWW  (32 * SLS)              // 576 words per 512-float row
#define WT_WORDS (JS * ROWW)          // 36864
#define HBUF_W   (BG * ROWW)          // 4608 words per h phase
#define PART_OFF (WT_WORDS + 2 * HBUF_W)    // 46080
#define RPS   18                      // partial row stride (16 cols + 2 pad)
#define SMEM_C ((PART_OFF + 512 * RPS) * 4) // 221184 bytes

typedef unsigned long long ull;

// ---------------- asm helpers ----------------

__device__ __forceinline__ unsigned smem_u32(const void* p) {
    return (unsigned)__cvta_generic_to_shared(p);
}

__device__ __forceinline__ ull lds64v(unsigned a) {
    ull v;
    asm volatile("ld.shared.b64 %0, [%1];" : "=l"(v) : "r"(a));
    return v;
}

__device__ __forceinline__ void sts32v(unsigned a, float v) {
    asm volatile("st.shared.f32 [%0], %1;" :: "r"(a), "f"(v) : "memory");
}

__device__ __forceinline__ float lds32v(unsigned a) {
    float v;
    asm volatile("ld.shared.f32 %0, [%1];" : "=f"(v) : "r"(a));
    return v;
}

__device__ __forceinline__ float4 lds128v(unsigned a) {
    float4 v;
    asm volatile("ld.shared.v4.f32 {%0,%1,%2,%3}, [%4];"
                 : "=f"(v.x), "=f"(v.y), "=f"(v.z), "=f"(v.w) : "r"(a));
    return v;
}

__device__ __forceinline__ ull dup2(float x) {
    unsigned xi = __float_as_uint(x);
    ull v;
    asm("mov.b64 %0, {%1, %1};" : "=l"(v) : "r"(xi));
    return v;
}

__device__ __forceinline__ float2 unpack2(ull v) {
    unsigned a, b;
    asm("mov.b64 {%0, %1}, %2;" : "=r"(a), "=r"(b) : "l"(v));
    return make_float2(__uint_as_float(a), __uint_as_float(b));
}

__device__ __forceinline__ void fma2(ull& acc, ull a, ull b) {
    asm("fma.rn.f32x2 %0, %1, %2, %0;" : "+l"(acc) : "l"(a), "l"(b));
}

__device__ __forceinline__ ull add2(ull a, ull b) {
    ull d;
    asm("add.rn.f32x2 %0, %1, %2;" : "=l"(d) : "l"(a), "l"(b));
    return d;
}

// ---------------- noop shim so ncu (4th kernel rule) captures the scan ---------

__global__ void noop_kernel_a() {}

// ---------------- Kernel A: xp = x @ W_ih^T + b_ih -> out[(b*T+t)*H + h] --------

__global__ void __launch_bounds__(256)
xp_gemm_kernel(const float* __restrict__ x, const float* __restrict__ W,
               const float* __restrict__ bias, float* __restrict__ out)
{
    __shared__ float As[2][16][64];
    __shared__ float Bs[2][16][64];

    const int tid = threadIdx.x;
    const int m0 = blockIdx.x * 64;
    const int h0 = blockIdx.y * 64;
    const int tx = tid & 15;
    const int ty = tid >> 4;
    const int ml = tid >> 2;
    const int kl = (tid & 3) * 4;

    ull acc[4][2];
#pragma unroll
    for (int i = 0; i < 4; i++) { acc[i][0] = 0ull; acc[i][1] = 0ull; }

    const float* xg = x + (size_t)(m0 + ml) * II + kl;
    const float* wg = W + (size_t)(h0 + ml) * II + kl;
    const unsigned aAddr0 = smem_u32(&As[0][0][ty * 4]);
    const unsigned bAddr0 = smem_u32(&Bs[0][0][tx * 4]);

    float4 xv = *(const float4*)(xg);
    float4 wv = *(const float4*)(wg);
    As[0][kl + 0][ml] = xv.x; As[0][kl + 1][ml] = xv.y;
    As[0][kl + 2][ml] = xv.z; As[0][kl + 3][ml] = xv.w;
    Bs[0][kl + 0][ml] = wv.x; Bs[0][kl + 1][ml] = wv.y;
    Bs[0][kl + 2][ml] = wv.z; Bs[0][kl + 3][ml] = wv.w;
    __syncthreads();

#pragma unroll 1
    for (int kt = 0; kt < 16; kt++) {
        const int p = kt & 1;
        if (kt + 1 < 16) {
            xv = *(const float4*)(xg + (kt + 1) * 16);
            wv = *(const float4*)(wg + (kt + 1) * 16);
        }
        const unsigned aAddr = aAddr0 + (unsigned)(p * 4096);
        const unsigned bAddr = bAddr0 + (unsigned)(p * 4096);
#pragma unroll
        for (int k = 0; k < 16; k++) {
            float4 a4 = lds128v(aAddr + (unsigned)(k * 256));
            ull b01 = lds64v(bAddr + (unsigned)(k * 256));
            ull b23 = lds64v(bAddr + (unsigned)(k * 256 + 8));
            ull d;
            d = dup2(a4.x); fma2(acc[0][0], b01, d); fma2(acc[0][1], b23, d);
            d = dup2(a4.y); fma2(acc[1][0], b01, d); fma2(acc[1][1], b23, d);
            d = dup2(a4.z); fma2(acc[2][0], b01, d); fma2(acc[2][1], b23, d);
            d = dup2(a4.w); fma2(acc[3][0], b01, d); fma2(acc[3][1], b23, d);
        }
        if (kt + 1 < 16) {
            const int q = p ^ 1;
            As[q][kl + 0][ml] = xv.x; As[q][kl + 1][ml] = xv.y;
            As[q][kl + 2][ml] = xv.z; As[q][kl + 3][ml] = xv.w;
            Bs[q][kl + 0][ml] = wv.x; Bs[q][kl + 1][ml] = wv.y;
            Bs[q][kl + 2][ml] = wv.z; Bs[q][kl + 3][ml] = wv.w;
            __syncthreads();
        }
    }

    const float2 bias01 = *(const float2*)&bias[h0 + tx * 4];
    const float2 bias23 = *(const float2*)&bias[h0 + tx * 4 + 2];
#pragma unroll
    for (int i = 0; i < 4; i++) {
        float2 c01 = unpack2(acc[i][0]);
        float2 c23 = unpack2(acc[i][1]);
        float4 res;
        res.x = c01.x + bias01.x;
        res.y = c01.y + bias01.y;
        res.z = c23.x + bias23.x;
        res.w = c23.y + bias23.y;
        *(float4*)&out[(size_t)(m0 + ty * 4 + i) * HH + h0 + tx * 4] = res;
    }
}

// ---------------- Kernel B ------------------------------------------------------

__device__ float g_cp[BB * HH];
__device__ float g_h[2][BB][HH];
__device__ int   g_cnt[2][NG][32];

__global__ void __launch_bounds__(512)
cp_kernel(const float* __restrict__ cons, const float* __restrict__ W_ch,
          const float* __restrict__ b_ch, const float* __restrict__ b_hh)
{
    __shared__ float cs[CC];
    const int b = blockIdx.x;
    const int h = threadIdx.x;
    if (h < CC) cs[h] = cons[b * CC + h];
    __syncthreads();
    float s = b_ch[h] + b_hh[h];
#pragma unroll
    for (int c = 0; c < CC; c++) s += cs[c] * W_ch[h * CC + c];
    g_cp[b * HH + h] = s;
}

// ---------------- Kernel C: recurrence, deep tile (8b x 8j x 16k / thread) ------
// 128 CTAs, 1/SM. Group g = 8 CTAs; CTA r holds W rows [64r, 64r+64) in SMEM.
// Warp wd owns j in [8wd, 8wd+8); lane l = k-slice (16 k). 64 f32x2 accs/thread.
// Crossbar/step: W 128KB once + h 16KB x 8 warps = 256KB -> ~2048 cyc (== FMA2
// floor). Reduce: fold + 1 shfl round (xor16) -> 16 partials/row in SMEM;
// final sum + tanh by (j, b-pair) owner thread; publish via L2 + counter sync.

__global__ void __launch_bounds__(256, 1)
rnn_scan_kernel(float* __restrict__ out, const float* __restrict__ W_hh,
                const int* __restrict__ lengths)
{
    extern __shared__ float smem[];

    const int tid = threadIdx.x;
    const int r = blockIdx.x & 7;
    const int g = blockIdx.x >> 3;

    // Load W slice: Wt[j][slice][16(+2)]
    for (int idx = tid; idx < JS * HH; idx += 256) {
        int j = idx >> 9;
        int k = idx & (HH - 1);
        smem[j * ROWW + (k >> 4) * SLS + (k & 15)] = W_hh[(r * JS + j) * HH + k];
    }
    // Zero h phase 0
    for (int idx = tid; idx < HBUF_W; idx += 256) smem[WT_WORDS + idx] = 0.0f;

    const int wd = tid >> 5;            // warp = j-octet (0..7)
    const int l = tid & 31;             // lane = k-slice (0..31)

    const unsigned sm_base = smem_u32(smem);
    const unsigned h_dot0 = sm_base + (unsigned)((WT_WORDS + l * SLS) * 4);
    const unsigned w_dot = sm_base + (unsigned)((wd * 8 * ROWW + l * SLS) * 4);
    const unsigned part_base = sm_base + (unsigned)(PART_OFF * 4);

    // final-phase identity: thread owns rows 2tid, 2tid+1:
    // row = j_local*8 + b  ->  j_local = tid>>2, b0 = (tid&3)*2
    const int jl = tid >> 2;
    const int b0 = (tid & 3) * 2;
    const int bg0 = g * BG + b0;
    const int bg1 = bg0 + 1;
    const int jg = r * JS + jl;
    const int len0 = lengths[bg0];
    const int len1 = lengths[bg1];
    const float cp0 = g_cp[bg0 * HH + jg];
    const float cp1 = g_cp[bg1 * HH + jg];

    float* out0 = out + (size_t)bg0 * TT * HH + jg;
    float* out1 = out + (size_t)bg1 * TT * HH + jg;
    float* last0 = out + (size_t)BB * TT * HH + (size_t)bg0 * HH + jg;
    float* last1 = out + (size_t)BB * TT * HH + (size_t)bg1 * HH + jg;

    const unsigned hold_w = (unsigned)(((jg >> 4) * SLS + (jg & 15)) * 4);
    const unsigned prow0 = part_base + (unsigned)(2 * tid * RPS * 4);
    const unsigned prow1 = prow0 + (unsigned)(RPS * 4);

    int* cnt1 = &g_cnt[1][g][0];
    int* cnt0 = &g_cnt[0][g][0];

    float xp0 = *out0;                   // prefetch xp for t=0
    float xp1 = *out1;

    __syncthreads();

    for (int t = 0; t < TT; t++) {
        const int p = t & 1;
        const int w = p ^ 1;
        const unsigned hb = h_dot0 + (unsigned)(p * (HBUF_W * 4));

        // ---- dot: acc[b][ji] f32x2 over (even k, odd k) in slice l ----
        ull acc[8][8];
#pragma unroll
        for (int b = 0; b < 8; b++)
#pragma unroll
            for (int ji = 0; ji < 8; ji++) acc[b][ji] = 0ull;

#pragma unroll
        for (int kp = 0; kp < 8; kp++) {
            ull hv[8], wv[8];
#pragma unroll
            for (int b = 0; b < 8; b++)
                hv[b] = lds64v(hb + (unsigned)(b * (ROWW * 4) + kp * 8));
#pragma unroll
            for (int ji = 0; ji < 8; ji++)
                wv[ji] = lds64v(w_dot + (unsigned)(ji * (ROWW * 4) + kp * 8));
#pragma unroll
            for (int b = 0; b < 8; b++)
#pragma unroll
                for (int ji = 0; ji < 8; ji++)
                    fma2(acc[b][ji], wv[ji], hv[b]);
        }

        // ---- reduce: fold f32x2, 1 shfl round (32 -> 16 partials per row) ----
#pragma unroll
        for (int b = 0; b < 8; b++)
#pragma unroll
            for (int ji = 0; ji < 8; ji++) {
                float2 f = unpack2(acc[b][ji]);
                float s = f.x + f.y;
                s += __shfl_xor_sync(0xffffffffu, s, 16);
                if (l < 16) {
                    int row = (wd * 8 + ji) * 8 + b;
                    sts32v(part_base + (unsigned)((row * RPS + l) * 4), s);
                }
            }
        __syncthreads();

        // ---- final: sum 16 partials for rows 2tid, 2tid+1, tanh, publish ----
        ull u0 = add2(add2(lds64v(prow0), lds64v(prow0 + 8)),
                      add2(lds64v(prow0 + 16), lds64v(prow0 + 24)));
        ull u0b = add2(add2(lds64v(prow0 + 32), lds64v(prow0 + 40)),
                       add2(lds64v(prow0 + 48), lds64v(prow0 + 56)));
        ull u1 = add2(add2(lds64v(prow1), lds64v(prow1 + 8)),
                      add2(lds64v(prow1 + 16), lds64v(prow1 + 24)));
        ull u1b = add2(add2(lds64v(prow1 + 32), lds64v(prow1 + 40)),
                       add2(lds64v(prow1 + 48), lds64v(prow1 + 56)));
        float2 f0 = unpack2(add2(u0, u0b));
        float2 f1 = unpack2(add2(u1, u1b));
        float d0 = f0.x + f0.y;
        float d1 = f1.x + f1.y;

        const unsigned hold_base = sm_base +
            (unsigned)((WT_WORDS + p * HBUF_W) * 4) + hold_w;
        float hold0 = lds32v(hold_base + (unsigned)(b0 * (ROWW * 4)));
        float hold1 = lds32v(hold_base + (unsigned)((b0 + 1) * (ROWW * 4)));

        const bool act0 = (t < len0);
        const bool act1 = (t < len1);
        float v0 = tanhf(d0 + xp0 + cp0);
        float v1 = tanhf(d1 + xp1 + cp1);
        float n0 = act0 ? v0 : hold0;
        float n1 = act1 ? v1 : hold1;

        __stcg(&g_h[w][bg0][jg], n0);     // publish (L2, bypass L1)
        __stcg(&g_h[w][bg1][jg], n1);

        out0[(size_t)t * HH] = act0 ? v0 : 0.0f;
        out1[(size_t)t * HH] = act1 ? v1 : 0.0f;
        if (t == len0 - 1) *last0 = v0;
        if (t == len1 - 1) *last1 = v1;

        if (t == TT - 1) break;

        xp0 = out0[(size_t)(t + 1) * HH];  // prefetch next xp under sync window
        xp1 = out1[(size_t)(t + 1) * HH];

        __syncthreads();
        if (tid == 0) {
            int* cw = w ? cnt1 : cnt0;
            asm volatile("red.release.gpu.global.add.s32 [%0], %1;"
                         :: "l"(cw), "r"(1) : "memory");
            const int target = ((t >> 1) + 1) * GR;
            int v;
            do {
                asm volatile("ld.acquire.gpu.global.s32 %0, [%1];"
                             : "=r"(v) : "l"(cw) : "memory");
            } while (v < target);
        }
        __syncthreads();

        // stage h for next step (L2-only float4 loads, v2 SMEM stores)
        {
            const unsigned dst0 = sm_base + (unsigned)((WT_WORDS + w * HBUF_W) * 4);
#pragma unroll
            for (int i = 0; i < 4; i++) {
                int idx = tid + i * 256;       // 0..1023 float4
                int b_i = idx >> 7;            // 0..7
                int k4 = (idx & 127) * 4;      // 0..508
                float4 v4 = __ldcg((const float4*)&g_h[w][g * BG + b_i][k4]);
                unsigned dw = dst0 +
                    (unsigned)((b_i * ROWW + (k4 >> 4) * SLS + (k4 & 15)) * 4);
                asm volatile("st.shared.v2.f32 [%0], {%1,%2};"
                             :: "r"(dw), "f"(v4.x), "f"(v4.y) : "memory");
                asm volatile("st.shared.v2.f32 [%0], {%1,%2};"
                             :: "r"(dw + 8), "f"(v4.z), "f"(v4.w) : "memory");
            }
        }
        __syncthreads();
    }
}

// ---------------- launch -------------------------------------------------------

extern "C" void kernel_launch(void* const* d_in, const int* in_sizes, int n_in,
                              void* d_out, int out_size)
{
    const float* x       = (const float*)d_in[0];
    const float* cons    = (const float*)d_in[1];
    const int*   lengths = (const int*)d_in[2];
    const float* W_ih    = (const float*)d_in[3];
    const float* b_ih    = (const float*)d_in[4];
    const float* W_hh    = (const float*)d_in[5];
    const float* b_hh    = (const float*)d_in[6];
    const float* W_ch    = (const float*)d_in[7];
    const float* b_ch    = (const float*)d_in[8];
    float* out = (float*)d_out;

    // Reset group counters
    void* cnt_addr = nullptr;
    cudaGetSymbolAddress(&cnt_addr, g_cnt);
    cudaMemsetAsync(cnt_addr, 0, sizeof(int) * 2 * NG * 32);

    // ncu lands on the 4th kernel: noop, xp, cp, scan
    noop_kernel_a<<<1, 32>>>();

    // Phase A: xp into the outputs region of d_out
    dim3 ga((BB * TT) / 64, HH / 64);
    xp_gemm_kernel<<<ga, 256>>>(x, W_ih, b_ih, out);

    // Phase B: cp
    cp_kernel<<<BB, HH>>>(cons, W_ch, b_ch, b_hh);

    // Phase C: recurrence (128 CTAs, 1 per SM, deep register tile)
    cudaFuncSetAttribute(rnn_scan_kernel,
                         cudaFuncAttributeMaxDynamicSharedMemorySize, SMEM_C);
    rnn_scan_kernel<<<BB, 256, SMEM_C>>>(out, W_hh, lengths);
}

// round 10
// speedup vs baseline: 2.7316x; 1.1533x over previous
#include <cuda_runtime.h>
#include <cuda_bf16.h>
#include <cstdint>

// Problem constants
#define BB   128
#define TT   1024
#define II   256
#define HH   512
#define CC   32

#define GR   8          // CTAs per group (W split 8 ways)
#define NG   16         // 16 groups (8 batches each)
#define BG   8          // batches per group
#define JS   64         // j rows per CTA

// scan smem geometry (units: 32-bit words)
#define SLS   18                      // words per 16-float k-slice (2 pad)
#define ROWW  (32 * SLS)              // 576 words per 512-float row
#define WT_WORDS (JS * ROWW)          // 36864
#define HBUF_W   (BG * ROWW)          // 4608 words per h phase
#define PART_OFF (WT_WORDS + 2 * HBUF_W)    // 46080
#define RPS   18                      // partial row stride (16 cols + 2 pad)
#define SMEM_C ((PART_OFF + 512 * RPS) * 4) // 221184 bytes

typedef unsigned long long ull;

// ---------------- generic asm helpers ----------------

__device__ __forceinline__ unsigned smem_u32(const void* p) {
    return (unsigned)__cvta_generic_to_shared(p);
}

__device__ __forceinline__ ull lds64v(unsigned a) {
    ull v;
    asm volatile("ld.shared.b64 %0, [%1];" : "=l"(v) : "r"(a));
    return v;
}

__device__ __forceinline__ void sts32v(unsigned a, float v) {
    asm volatile("st.shared.f32 [%0], %1;" :: "r"(a), "f"(v) : "memory");
}

__device__ __forceinline__ float lds32v(unsigned a) {
    float v;
    asm volatile("ld.shared.f32 %0, [%1];" : "=f"(v) : "r"(a));
    return v;
}

__device__ __forceinline__ void sts128v(unsigned a, uint4 v) {
    asm volatile("st.shared.v4.b32 [%0], {%1,%2,%3,%4};"
                 :: "r"(a), "r"(v.x), "r"(v.y), "r"(v.z), "r"(v.w) : "memory");
}

__device__ __forceinline__ float2 unpack2(ull v) {
    unsigned a, b;
    asm("mov.b64 {%0, %1}, %2;" : "=r"(a), "=r"(b) : "l"(v));
    return make_float2(__uint_as_float(a), __uint_as_float(b));
}

__device__ __forceinline__ void fma2(ull& acc, ull a, ull b) {
    asm("fma.rn.f32x2 %0, %1, %2, %0;" : "+l"(acc) : "l"(a), "l"(b));
}

__device__ __forceinline__ ull add2(ull a, ull b) {
    ull d;
    asm("add.rn.f32x2 %0, %1, %2;" : "=l"(d) : "l"(a), "l"(b));
    return d;
}

__device__ __forceinline__ void ldsm_x4(unsigned addr, uint32_t& r0, uint32_t& r1,
                                        uint32_t& r2, uint32_t& r3) {
    asm volatile("ldmatrix.sync.aligned.m8n8.x4.shared.b16 {%0,%1,%2,%3}, [%4];"
                 : "=r"(r0), "=r"(r1), "=r"(r2), "=r"(r3) : "r"(addr));
}

__device__ __forceinline__ void mma16816(float* c, const uint32_t* a,
                                         uint32_t b0, uint32_t b1) {
    asm volatile(
        "mma.sync.aligned.m16n8k16.row.col.f32.bf16.bf16.f32 "
        "{%0,%1,%2,%3}, {%4,%5,%6,%7}, {%8,%9}, {%0,%1,%2,%3};"
        : "+f"(c[0]), "+f"(c[1]), "+f"(c[2]), "+f"(c[3])
        : "r"(a[0]), "r"(a[1]), "r"(a[2]), "r"(a[3]), "r"(b0), "r"(b1));
}

// ---------------- Pre-pass: split x and W_ih into bf16 hi/lo ----------------

#define NX4 ((BB * TT * II) / 4)   // 8388608 float4 groups
#define NW4 ((HH * II) / 4)        // 32768

__device__ __nv_bfloat16 g_xhi[BB * TT * II];
__device__ __nv_bfloat16 g_xlo[BB * TT * II];
__device__ __nv_bfloat16 g_whi[HH * II];
__device__ __nv_bfloat16 g_wlo[HH * II];

__global__ void __launch_bounds__(256)
cvt_kernel(const float* __restrict__ x, const float* __restrict__ w)
{
    const int stride = gridDim.x * blockDim.x;
    for (int i = blockIdx.x * blockDim.x + threadIdx.x; i < NX4 + NW4; i += stride) {
        float4 v = (i < NX4) ? ((const float4*)x)[i]
                             : ((const float4*)w)[i - NX4];
        __nv_bfloat162 h01 = __floats2bfloat162_rn(v.x, v.y);
        __nv_bfloat162 h23 = __floats2bfloat162_rn(v.z, v.w);
        float l0 = v.x - __bfloat162float(h01.x);
        float l1 = v.y - __bfloat162float(h01.y);
        float l2 = v.z - __bfloat162float(h23.x);
        float l3 = v.w - __bfloat162float(h23.y);
        __nv_bfloat162 q01 = __floats2bfloat162_rn(l0, l1);
        __nv_bfloat162 q23 = __floats2bfloat162_rn(l2, l3);
        uint2 hv = make_uint2(*(uint32_t*)&h01, *(uint32_t*)&h23);
        uint2 lv = make_uint2(*(uint32_t*)&q01, *(uint32_t*)&q23);
        if (i < NX4) {
            ((uint2*)g_xhi)[i] = hv;
            ((uint2*)g_xlo)[i] = lv;
        } else {
            ((uint2*)g_whi)[i - NX4] = hv;
            ((uint2*)g_wlo)[i - NX4] = lv;
        }
    }
}

// ---------------- Kernel A: xp via mma.sync bf16 split-precision ---------------
// CTA: 128m x 64n, K in 4 chunks of 64 staged in SMEM (stride 72 bf16, so
// ldmatrix row addresses hit distinct 16B banks). Warps 4m x 2n; warp tile
// 32x32 = 2 m16 x 4 n8 tiles; 3 MMAs per tile pair (hi*hi + hi*lo + lo*hi).

#define KC     64
#define ASTR   72                     // bf16 stride
#define XA_HI  0
#define XA_LO  (128 * ASTR * 2)       // 18432
#define XB_HI  (2 * 128 * ASTR * 2)   // 36864
#define XB_LO  (XB_HI + 64 * ASTR * 2)
#define SMEM_X (XB_LO + 64 * ASTR * 2)  // 55296 bytes

__global__ void __launch_bounds__(256)
xp_mma_kernel(const float* __restrict__ bias, float* __restrict__ out)
{
    extern __shared__ char smx[];
    const unsigned sb = smem_u32(smx);
    const int tid = threadIdx.x;
    const int wid = tid >> 5;
    const int lane = tid & 31;
    const int h0 = blockIdx.x * 64;            // n-tile (8)
    const int m0 = blockIdx.y * 128;           // m-tile (1024)

    const int wr = wid >> 1;                   // warp m index (0..3)
    const int wc = wid & 1;                    // warp n index (0..1)

    float acc[2][4][4];
#pragma unroll
    for (int mt = 0; mt < 2; mt++)
#pragma unroll
        for (int nt = 0; nt < 4; nt++)
#pragma unroll
            for (int i = 0; i < 4; i++) acc[mt][nt][i] = 0.0f;

    // ldmatrix per-thread base addresses (element units within tile)
    const int a_row = wr * 32 + (lane & 15);
    const int a_col = (lane >> 4) * 8;
    const unsigned a_addr0 = sb + XA_HI + (unsigned)((a_row * ASTR + a_col) * 2);
    const int b_n = wc * 32 + (lane & 7) + (lane >> 4) * 8;
    const int b_k = ((lane >> 3) & 1) * 8;
    const unsigned b_addr0 = sb + XB_HI + (unsigned)((b_n * ASTR + b_k) * 2);

    for (int ch = 0; ch < 4; ch++) {
        __syncthreads();
        // stage A (x_hi/x_lo): 128 rows x 64 bf16 each
        {
#pragma unroll
            for (int i = 0; i < 4; i++) {
                int idx = tid + i * 256;       // 0..1023 uint4
                int row = idx >> 3;
                int c8 = idx & 7;
                size_t src = (size_t)(m0 + row) * II + ch * KC + c8 * 8;
                unsigned dst = (unsigned)((row * ASTR + c8 * 8) * 2);
                sts128v(sb + XA_HI + dst, *(const uint4*)(g_xhi + src));
                sts128v(sb + XA_LO + dst, *(const uint4*)(g_xlo + src));
            }
        }
        // stage B (W_hi/W_lo): 64 rows x 64 bf16 each
        {
#pragma unroll
            for (int i = 0; i < 2; i++) {
                int idx = tid + i * 256;       // 0..511 uint4
                int row = idx >> 3;
                int c8 = idx & 7;
                size_t src = (size_t)(h0 + row) * II + ch * KC + c8 * 8;
                unsigned dst = (unsigned)((row * ASTR + c8 * 8) * 2);
                sts128v(sb + XB_HI + dst, *(const uint4*)(g_whi + src));
                sts128v(sb + XB_LO + dst, *(const uint4*)(g_wlo + src));
            }
        }
        __syncthreads();

#pragma unroll
        for (int kk = 0; kk < 4; kk++) {
            const unsigned akk = (unsigned)(kk * 16 * 2);
            const unsigned bkk = (unsigned)(kk * 16 * 2);
            uint32_t ah[2][4], al[2][4];
#pragma unroll
            for (int mt = 0; mt < 2; mt++) {
                unsigned ao = a_addr0 + akk + (unsigned)(mt * 16 * ASTR * 2);
                ldsm_x4(ao, ah[mt][0], ah[mt][1], ah[mt][2], ah[mt][3]);
                ldsm_x4(ao + (XA_LO - XA_HI),
                        al[mt][0], al[mt][1], al[mt][2], al[mt][3]);
            }
            uint32_t bh[2][4], bl[2][4];
#pragma unroll
            for (int np = 0; np < 2; np++) {
                unsigned bo = b_addr0 + bkk + (unsigned)(np * 16 * ASTR * 2);
                ldsm_x4(bo, bh[np][0], bh[np][1], bh[np][2], bh[np][3]);
                ldsm_x4(bo + (XB_LO - XB_HI),
                        bl[np][0], bl[np][1], bl[np][2], bl[np][3]);
            }
#pragma unroll
            for (int mt = 0; mt < 2; mt++)
#pragma unroll
                for (int np = 0; np < 2; np++)
#pragma unroll
                    for (int sub = 0; sub < 2; sub++) {
                        float* c = acc[mt][np * 2 + sub];
                        mma16816(c, ah[mt], bh[np][sub * 2], bh[np][sub * 2 + 1]);
                        mma16816(c, ah[mt], bl[np][sub * 2], bl[np][sub * 2 + 1]);
                        mma16816(c, al[mt], bh[np][sub * 2], bh[np][sub * 2 + 1]);
                    }
        }
    }

    // epilogue: c fragment (g = lane>>2 row, tig = lane&3 col-pair)
    const int g = lane >> 2;
    const int tig = lane & 3;
#pragma unroll
    for (int mt = 0; mt < 2; mt++) {
        const int row0 = m0 + wr * 32 + mt * 16 + g;
#pragma unroll
        for (int nt = 0; nt < 4; nt++) {
            const int col = h0 + wc * 32 + nt * 8 + tig * 2;
            float2 bv = *(const float2*)&bias[col];
            float* c = acc[mt][nt];
            float2 o0 = make_float2(c[0] + bv.x, c[1] + bv.y);
            float2 o1 = make_float2(c[2] + bv.x, c[3] + bv.y);
            *(float2*)&out[(size_t)row0 * HH + col] = o0;
            *(float2*)&out[(size_t)(row0 + 8) * HH + col] = o1;
        }
    }
}

// ---------------- Kernel B ------------------------------------------------------

__device__ float g_cp[BB * HH];
__device__ float g_h[2][BB][HH];
__device__ int   g_cnt[2][NG][32];

__global__ void __launch_bounds__(512)
cp_kernel(const float* __restrict__ cons, const float* __restrict__ W_ch,
          const float* __restrict__ b_ch, const float* __restrict__ b_hh)
{
    __shared__ float cs[CC];
    const int b = blockIdx.x;
    const int h = threadIdx.x;
    if (h < CC) cs[h] = cons[b * CC + h];
    __syncthreads();
    float s = b_ch[h] + b_hh[h];
#pragma unroll
    for (int c = 0; c < CC; c++) s += cs[c] * W_ch[h * CC + c];
    g_cp[b * HH + h] = s;
}

// ---------------- Kernel C: recurrence (R8 layout, intra-warp final) -------------

__global__ void __launch_bounds__(256, 1)
rnn_scan_kernel(float* __restrict__ out, const float* __restrict__ W_hh,
                const int* __restrict__ lengths)
{
    extern __shared__ float smem[];

    const int tid = threadIdx.x;
    const int r = blockIdx.x & 7;
    const int g = blockIdx.x >> 3;

    for (int idx = tid; idx < JS * HH; idx += 256) {
        int j = idx >> 9;
        int k = idx & (HH - 1);
        smem[j * ROWW + (k >> 4) * SLS + (k & 15)] = W_hh[(r * JS + j) * HH + k];
    }
    for (int idx = tid; idx < HBUF_W; idx += 256) smem[WT_WORDS + idx] = 0.0f;

    const int wd = tid >> 5;
    const int l = tid & 31;

    const unsigned sm_base = smem_u32(smem);
    const unsigned h_dot0 = sm_base + (unsigned)((WT_WORDS + l * SLS) * 4);
    const unsigned w_dot = sm_base + (unsigned)((wd * 8 * ROWW + l * SLS) * 4);
    const unsigned part_base = sm_base + (unsigned)(PART_OFF * 4);

    const int jl = tid >> 2;
    const int b0 = (tid & 3) * 2;
    const int bg0 = g * BG + b0;
    const int bg1 = bg0 + 1;
    const int jg = r * JS + jl;
    const int len0 = lengths[bg0];
    const int len1 = lengths[bg1];
    const float cp0 = g_cp[bg0 * HH + jg];
    const float cp1 = g_cp[bg1 * HH + jg];

    float* out0 = out + (size_t)bg0 * TT * HH + jg;
    float* out1 = out + (size_t)bg1 * TT * HH + jg;
    float* last0 = out + (size_t)BB * TT * HH + (size_t)bg0 * HH + jg;
    float* last1 = out + (size_t)BB * TT * HH + (size_t)bg1 * HH + jg;

    const unsigned hold_w = (unsigned)(((jg >> 4) * SLS + (jg & 15)) * 4);
    const unsigned prow0 = part_base + (unsigned)(2 * tid * RPS * 4);
    const unsigned prow1 = prow0 + (unsigned)(RPS * 4);

    int* cnt1 = &g_cnt[1][g][0];
    int* cnt0 = &g_cnt[0][g][0];

    float xp0 = *out0;
    float xp1 = *out1;

    __syncthreads();

    for (int t = 0; t < TT; t++) {
        const int p = t & 1;
        const int w = p ^ 1;
        const unsigned hb = h_dot0 + (unsigned)(p * (HBUF_W * 4));

        ull acc[8][8];
#pragma unroll
        for (int b = 0; b < 8; b++)
#pragma unroll
            for (int ji = 0; ji < 8; ji++) acc[b][ji] = 0ull;

#pragma unroll
        for (int kp = 0; kp < 8; kp++) {
            ull hv[8], wv[8];
#pragma unroll
            for (int b = 0; b < 8; b++)
                hv[b] = lds64v(hb + (unsigned)(b * (ROWW * 4) + kp * 8));
#pragma unroll
            for (int ji = 0; ji < 8; ji++)
                wv[ji] = lds64v(w_dot + (unsigned)(ji * (ROWW * 4) + kp * 8));
#pragma unroll
            for (int b = 0; b < 8; b++)
#pragma unroll
                for (int ji = 0; ji < 8; ji++)
                    fma2(acc[b][ji], wv[ji], hv[b]);
        }

#pragma unroll
        for (int b = 0; b < 8; b++)
#pragma unroll
            for (int ji = 0; ji < 8; ji++) {
                float2 f = unpack2(acc[b][ji]);
                float s = f.x + f.y;
                s += __shfl_xor_sync(0xffffffffu, s, 16);
                if (l < 16) {
                    int row = (wd * 8 + ji) * 8 + b;
                    sts32v(part_base + (unsigned)((row * RPS + l) * 4), s);
                }
            }
        __syncwarp();   // partials and final rows are intra-warp

        ull u0 = add2(add2(lds64v(prow0), lds64v(prow0 + 8)),
                      add2(lds64v(prow0 + 16), lds64v(prow0 + 24)));
        ull u0b = add2(add2(lds64v(prow0 + 32), lds64v(prow0 + 40)),
                       add2(lds64v(prow0 + 48), lds64v(prow0 + 56)));
        ull u1 = add2(add2(lds64v(prow1), lds64v(prow1 + 8)),
                      add2(lds64v(prow1 + 16), lds64v(prow1 + 24)));
        ull u1b = add2(add2(lds64v(prow1 + 32), lds64v(prow1 + 40)),
                       add2(lds64v(prow1 + 48), lds64v(prow1 + 56)));
        float2 f0 = unpack2(add2(u0, u0b));
        float2 f1 = unpack2(add2(u1, u1b));
        float d0 = f0.x + f0.y;
        float d1 = f1.x + f1.y;

        const unsigned hold_base = sm_base +
            (unsigned)((WT_WORDS + p * HBUF_W) * 4) + hold_w;
        float hold0 = lds32v(hold_base + (unsigned)(b0 * (ROWW * 4)));
        float hold1 = lds32v(hold_base + (unsigned)((b0 + 1) * (ROWW * 4)));

        const bool act0 = (t < len0);
        const bool act1 = (t < len1);
        float v0 = tanhf(d0 + xp0 + cp0);
        float v1 = tanhf(d1 + xp1 + cp1);
        float n0 = act0 ? v0 : hold0;
        float n1 = act1 ? v1 : hold1;

        __stcg(&g_h[w][bg0][jg], n0);
        __stcg(&g_h[w][bg1][jg], n1);

        out0[(size_t)t * HH] = act0 ? v0 : 0.0f;
        out1[(size_t)t * HH] = act1 ? v1 : 0.0f;
        if (t == len0 - 1) *last0 = v0;
        if (t == len1 - 1) *last1 = v1;

        if (t == TT - 1) break;

        xp0 = out0[(size_t)(t + 1) * HH];
        xp1 = out1[(size_t)(t + 1) * HH];

        __syncthreads();
        if (tid == 0) {
            int* cw = w ? cnt1 : cnt0;
            asm volatile("red.release.gpu.global.add.s32 [%0], %1;"
                         :: "l"(cw), "r"(1) : "memory");
            const int target = ((t >> 1) + 1) * GR;
            int v;
            do {
                asm volatile("ld.acquire.gpu.global.s32 %0, [%1];"
                             : "=r"(v) : "l"(cw) : "memory");
            } while (v < target);
        }
        __syncthreads();

        {
            const unsigned dst0 = sm_base + (unsigned)((WT_WORDS + w * HBUF_W) * 4);
#pragma unroll
            for (int i = 0; i < 4; i++) {
                int idx = tid + i * 256;
                int b_i = idx >> 7;
                int k4 = (idx & 127) * 4;
                float4 v4 = __ldcg((const float4*)&g_h[w][g * BG + b_i][k4]);
                unsigned dw = dst0 +
                    (unsigned)((b_i * ROWW + (k4 >> 4) * SLS + (k4 & 15)) * 4);
                asm volatile("st.shared.v2.f32 [%0], {%1,%2};"
                             :: "r"(dw), "f"(v4.x), "f"(v4.y) : "memory");
                asm volatile("st.shared.v2.f32 [%0], {%1,%2};"
                             :: "r"(dw + 8), "f"(v4.z), "f"(v4.w) : "memory");
            }
        }
        __syncthreads();
    }
}

// ---------------- launch -------------------------------------------------------

extern "C" void kernel_launch(void* const* d_in, const int* in_sizes, int n_in,
                              void* d_out, int out_size)
{
    const float* x       = (const float*)d_in[0];
    const float* cons    = (const float*)d_in[1];
    const int*   lengths = (const int*)d_in[2];
    const float* W_ih    = (const float*)d_in[3];
    const float* b_ih    = (const float*)d_in[4];
    const float* W_hh    = (const float*)d_in[5];
    const float* b_hh    = (const float*)d_in[6];
    const float* W_ch    = (const float*)d_in[7];
    const float* b_ch    = (const float*)d_in[8];
    float* out = (float*)d_out;

    // Reset group counters
    void* cnt_addr = nullptr;
    cudaGetSymbolAddress(&cnt_addr, g_cnt);
    cudaMemsetAsync(cnt_addr, 0, sizeof(int) * 2 * NG * 32);

    // Kernel order (ncu lands on the 4th kernel -> scan): cvt, xp, cp, scan
    cvt_kernel<<<4096, 256>>>(x, W_ih);

    // Phase A: xp = x @ W_ih^T + b_ih via mma.sync (bf16 split-precision)
    cudaFuncSetAttribute(xp_mma_kernel,
                         cudaFuncAttributeMaxDynamicSharedMemorySize, SMEM_X);
    xp_mma_kernel<<<dim3(8, (BB * TT) / 128), 256, SMEM_X>>>(b_ih, out);

    // Phase B: cp
    cp_kernel<<<BB, HH>>>(cons, W_ch, b_ch, b_hh);

    // Phase C: recurrence
    cudaFuncSetAttribute(rnn_scan_kernel,
                         cudaFuncAttributeMaxDynamicSharedMemorySize, SMEM_C);
    rnn_scan_kernel<<<BB, 256, SMEM_C>>>(out, W_hh, lengths);
}

// round 11
// speedup vs baseline: 3.5935x; 1.3155x over previous
#include <cuda_runtime.h>
#include <cuda_bf16.h>
#include <cstdint>

// Problem constants
#define BB   128
#define TT   1024
#define II   256
#define HH   512
#define CC   32

#define GR   8          // CTAs per group (W split 8 ways)
#define NG   16         // 16 groups (8 batches each)
#define BG   8          // batches per group
#define JS   64         // j rows per CTA

typedef unsigned long long ull;

// ---------------- generic asm helpers ----------------

__device__ __forceinline__ unsigned smem_u32(const void* p) {
    return (unsigned)__cvta_generic_to_shared(p);
}

__device__ __forceinline__ float lds32v(unsigned a) {
    float v;
    asm volatile("ld.shared.f32 %0, [%1];" : "=f"(v) : "r"(a));
    return v;
}

__device__ __forceinline__ void sts128v(unsigned a, uint4 v) {
    asm volatile("st.shared.v4.b32 [%0], {%1,%2,%3,%4};"
                 :: "r"(a), "r"(v.x), "r"(v.y), "r"(v.z), "r"(v.w) : "memory");
}

__device__ __forceinline__ void sts64u(unsigned a, uint32_t x, uint32_t y) {
    asm volatile("st.shared.v2.b32 [%0], {%1,%2};"
                 :: "r"(a), "r"(x), "r"(y) : "memory");
}

__device__ __forceinline__ void sts64f(unsigned a, float x, float y) {
    asm volatile("st.shared.v2.f32 [%0], {%1,%2};"
                 :: "r"(a), "f"(x), "f"(y) : "memory");
}

__device__ __forceinline__ void ldsm_x4(unsigned addr, uint32_t& r0, uint32_t& r1,
                                        uint32_t& r2, uint32_t& r3) {
    asm volatile("ldmatrix.sync.aligned.m8n8.x4.shared.b16 {%0,%1,%2,%3}, [%4];"
                 : "=r"(r0), "=r"(r1), "=r"(r2), "=r"(r3) : "r"(addr));
}

__device__ __forceinline__ void ldsm_x2(unsigned addr, uint32_t& r0, uint32_t& r1) {
    asm volatile("ldmatrix.sync.aligned.m8n8.x2.shared.b16 {%0,%1}, [%2];"
                 : "=r"(r0), "=r"(r1) : "r"(addr));
}

__device__ __forceinline__ void mma16816(float* c, const uint32_t* a,
                                         uint32_t b0, uint32_t b1) {
    asm volatile(
        "mma.sync.aligned.m16n8k16.row.col.f32.bf16.bf16.f32 "
        "{%0,%1,%2,%3}, {%4,%5,%6,%7}, {%8,%9}, {%0,%1,%2,%3};"
        : "+f"(c[0]), "+f"(c[1]), "+f"(c[2]), "+f"(c[3])
        : "r"(a[0]), "r"(a[1]), "r"(a[2]), "r"(a[3]), "r"(b0), "r"(b1));
}

// split a float4 into bf16x2 hi/lo register pairs
__device__ __forceinline__ void split4(float4 v, uint2& hv, uint2& lv) {
    __nv_bfloat162 h01 = __floats2bfloat162_rn(v.x, v.y);
    __nv_bfloat162 h23 = __floats2bfloat162_rn(v.z, v.w);
    float l0 = v.x - __bfloat162float(h01.x);
    float l1 = v.y - __bfloat162float(h01.y);
    float l2 = v.z - __bfloat162float(h23.x);
    float l3 = v.w - __bfloat162float(h23.y);
    __nv_bfloat162 q01 = __floats2bfloat162_rn(l0, l1);
    __nv_bfloat162 q23 = __floats2bfloat162_rn(l2, l3);
    hv = make_uint2(*(uint32_t*)&h01, *(uint32_t*)&h23);
    lv = make_uint2(*(uint32_t*)&q01, *(uint32_t*)&q23);
}

// ---------------- Pre-pass: split x and W_ih into bf16 hi/lo ----------------

#define NX4 ((BB * TT * II) / 4)   // 8388608 float4 groups
#define NW4 ((HH * II) / 4)        // 32768

__device__ __nv_bfloat16 g_xhi[BB * TT * II];
__device__ __nv_bfloat16 g_xlo[BB * TT * II];
__device__ __nv_bfloat16 g_whi[HH * II];
__device__ __nv_bfloat16 g_wlo[HH * II];

__global__ void __launch_bounds__(256)
cvt_kernel(const float* __restrict__ x, const float* __restrict__ w)
{
    const int stride = gridDim.x * blockDim.x;
    for (int i = blockIdx.x * blockDim.x + threadIdx.x; i < NX4 + NW4; i += stride) {
        float4 v = (i < NX4) ? ((const float4*)x)[i]
                             : ((const float4*)w)[i - NX4];
        uint2 hv, lv;
        split4(v, hv, lv);
        if (i < NX4) {
            ((uint2*)g_xhi)[i] = hv;
            ((uint2*)g_xlo)[i] = lv;
        } else {
            ((uint2*)g_whi)[i - NX4] = hv;
            ((uint2*)g_wlo)[i - NX4] = lv;
        }
    }
}

// ---------------- Kernel A: xp via mma.sync bf16 split-precision (R10) ---------

#define KC     64
#define ASTR   72                     // bf16 stride
#define XA_HI  0
#define XA_LO  (128 * ASTR * 2)       // 18432
#define XB_HI  (2 * 128 * ASTR * 2)   // 36864
#define XB_LO  (XB_HI + 64 * ASTR * 2)
#define SMEM_X (XB_LO + 64 * ASTR * 2)  // 55296 bytes

__global__ void __launch_bounds__(256)
xp_mma_kernel(const float* __restrict__ bias, float* __restrict__ out)
{
    extern __shared__ char smx[];
    const unsigned sb = smem_u32(smx);
    const int tid = threadIdx.x;
    const int wid = tid >> 5;
    const int lane = tid & 31;
    const int h0 = blockIdx.x * 64;
    const int m0 = blockIdx.y * 128;

    const int wr = wid >> 1;
    const int wc = wid & 1;

    float acc[2][4][4];
#pragma unroll
    for (int mt = 0; mt < 2; mt++)
#pragma unroll
        for (int nt = 0; nt < 4; nt++)
#pragma unroll
            for (int i = 0; i < 4; i++) acc[mt][nt][i] = 0.0f;

    const int a_row = wr * 32 + (lane & 15);
    const int a_col = (lane >> 4) * 8;
    const unsigned a_addr0 = sb + XA_HI + (unsigned)((a_row * ASTR + a_col) * 2);
    const int b_n = wc * 32 + (lane & 7) + (lane >> 4) * 8;
    const int b_k = ((lane >> 3) & 1) * 8;
    const unsigned b_addr0 = sb + XB_HI + (unsigned)((b_n * ASTR + b_k) * 2);

    for (int ch = 0; ch < 4; ch++) {
        __syncthreads();
        {
#pragma unroll
            for (int i = 0; i < 4; i++) {
                int idx = tid + i * 256;
                int row = idx >> 3;
                int c8 = idx & 7;
                size_t src = (size_t)(m0 + row) * II + ch * KC + c8 * 8;
                unsigned dst = (unsigned)((row * ASTR + c8 * 8) * 2);
                sts128v(sb + XA_HI + dst, *(const uint4*)(g_xhi + src));
                sts128v(sb + XA_LO + dst, *(const uint4*)(g_xlo + src));
            }
        }
        {
#pragma unroll
            for (int i = 0; i < 2; i++) {
                int idx = tid + i * 256;
                int row = idx >> 3;
                int c8 = idx & 7;
                size_t src = (size_t)(h0 + row) * II + ch * KC + c8 * 8;
                unsigned dst = (unsigned)((row * ASTR + c8 * 8) * 2);
                sts128v(sb + XB_HI + dst, *(const uint4*)(g_whi + src));
                sts128v(sb + XB_LO + dst, *(const uint4*)(g_wlo + src));
            }
        }
        __syncthreads();

#pragma unroll
        for (int kk = 0; kk < 4; kk++) {
            const unsigned akk = (unsigned)(kk * 16 * 2);
            uint32_t ah[2][4], al[2][4];
#pragma unroll
            for (int mt = 0; mt < 2; mt++) {
                unsigned ao = a_addr0 + akk + (unsigned)(mt * 16 * ASTR * 2);
                ldsm_x4(ao, ah[mt][0], ah[mt][1], ah[mt][2], ah[mt][3]);
                ldsm_x4(ao + (XA_LO - XA_HI),
                        al[mt][0], al[mt][1], al[mt][2], al[mt][3]);
            }
            uint32_t bh[2][4], bl[2][4];
#pragma unroll
            for (int np = 0; np < 2; np++) {
                unsigned bo = b_addr0 + akk + (unsigned)(np * 16 * ASTR * 2);
                ldsm_x4(bo, bh[np][0], bh[np][1], bh[np][2], bh[np][3]);
                ldsm_x4(bo + (XB_LO - XB_HI),
                        bl[np][0], bl[np][1], bl[np][2], bl[np][3]);
            }
#pragma unroll
            for (int mt = 0; mt < 2; mt++)
#pragma unroll
                for (int np = 0; np < 2; np++)
#pragma unroll
                    for (int sub = 0; sub < 2; sub++) {
                        float* c = acc[mt][np * 2 + sub];
                        mma16816(c, ah[mt], bh[np][sub * 2], bh[np][sub * 2 + 1]);
                        mma16816(c, ah[mt], bl[np][sub * 2], bl[np][sub * 2 + 1]);
                        mma16816(c, al[mt], bh[np][sub * 2], bh[np][sub * 2 + 1]);
                    }
        }
    }

    const int g = lane >> 2;
    const int tig = lane & 3;
#pragma unroll
    for (int mt = 0; mt < 2; mt++) {
        const int row0 = m0 + wr * 32 + mt * 16 + g;
#pragma unroll
        for (int nt = 0; nt < 4; nt++) {
            const int col = h0 + wc * 32 + nt * 8 + tig * 2;
            float2 bv = *(const float2*)&bias[col];
            float* c = acc[mt][nt];
            float2 o0 = make_float2(c[0] + bv.x, c[1] + bv.y);
            float2 o1 = make_float2(c[2] + bv.x, c[3] + bv.y);
            *(float2*)&out[(size_t)row0 * HH + col] = o0;
            *(float2*)&out[(size_t)(row0 + 8) * HH + col] = o1;
        }
    }
}

// ---------------- Kernel B ------------------------------------------------------

__device__ float g_cp[BB * HH];
__device__ float g_h[2][BB][HH];
__device__ int   g_cnt[2][NG][32];

__global__ void __launch_bounds__(512)
cp_kernel(const float* __restrict__ cons, const float* __restrict__ W_ch,
          const float* __restrict__ b_ch, const float* __restrict__ b_hh)
{
    __shared__ float cs[CC];
    const int b = blockIdx.x;
    const int h = threadIdx.x;
    if (h < CC) cs[h] = cons[b * CC + h];
    __syncthreads();
    float s = b_ch[h] + b_hh[h];
#pragma unroll
    for (int c = 0; c < CC; c++) s += cs[c] * W_ch[h * CC + c];
    g_cp[b * HH + h] = s;
}

// ---------------- Kernel C: recurrence via tensor cores -------------------------
// Per CTA (group g, rank r): D[64j,8b] = Wslice[64,512] @ h^T via bf16 split
// mma.sync (W=hi+lo converted once into SMEM; h converted each step in stage).
// 8 warps = 4 m-tiles x 2 k-halves; 2-way k reduce via small frag buffer.
// No h freeze: inactive steps' h values only feed masked outputs.

#define WSTR    520                   // bf16 row stride (1040B == 16 mod 128)
#define WHI_OFF 0
#define WLO_OFF (JS * WSTR * 2)       // 66560
#define HHI_OFF (2 * JS * WSTR * 2)   // 133120
#define HLO_OFF (HHI_OFF + BG * WSTR * 2)  // 141440
#define FRAG_OFF (HLO_OFF + BG * WSTR * 2) // 149760
#define FRW     10                    // frag row stride (floats)
#define SMEM_C  (FRAG_OFF + 2 * JS * FRW * 4 + 128)  // ~155 KB

__global__ void __launch_bounds__(256, 1)
rnn_scan_kernel(float* __restrict__ out, const float* __restrict__ W_hh,
                const int* __restrict__ lengths)
{
    extern __shared__ char smc[];
    const unsigned sb = smem_u32(smc);
    const int tid = threadIdx.x;
    const int r = blockIdx.x & 7;
    const int g = blockIdx.x >> 3;

    // one-time: convert W slice to bf16 hi/lo in SMEM
    for (int idx = tid; idx < (JS * HH) / 4; idx += 256) {
        int j = idx >> 7;
        int k4 = (idx & 127) * 4;
        float4 v = *(const float4*)&W_hh[(size_t)(r * JS + j) * HH + k4];
        uint2 hv, lv;
        split4(v, hv, lv);
        unsigned dst = sb + WHI_OFF + (unsigned)((j * WSTR + k4) * 2);
        sts64u(dst, hv.x, hv.y);
        sts64u(dst + (WLO_OFF - WHI_OFF), lv.x, lv.y);
    }
    // zero h hi/lo (h at t=0 is 0)
    for (int idx = tid; idx < (2 * BG * WSTR * 2) / 4; idx += 256) {
        asm volatile("st.shared.b32 [%0], %1;"
                     :: "r"(sb + HHI_OFF + (unsigned)(idx * 4)), "r"(0u) : "memory");
    }

    const int wid = tid >> 5;
    const int lane = tid & 31;
    const int mt = wid >> 1;            // m-tile (0..3)
    const int kh = wid & 1;             // k-half (0..1)

    // static ldmatrix addresses (validated maps from xp kernel)
    const unsigned aHi = sb + WHI_OFF +
        (unsigned)(((mt * 16 + (lane & 15)) * WSTR + kh * 256 + (lane >> 4) * 8) * 2);
    const unsigned aLo = aHi + (WLO_OFF - WHI_OFF);
    const int l4 = lane & 15;
    const unsigned bHi = sb + HHI_OFF +
        (unsigned)(((l4 & 7) * WSTR + kh * 256 + ((l4 >> 3) & 1) * 8) * 2);
    const unsigned bLo = bHi + (HLO_OFF - HHI_OFF);

    // frag store addrs
    const unsigned fr0 = sb + FRAG_OFF +
        (unsigned)(((kh * JS + mt * 16 + (lane >> 2)) * FRW + (lane & 3) * 2) * 4);
    const unsigned fr1 = fr0 + (unsigned)(8 * FRW * 4);

    // output identity: thread owns (j0 = tid>>3, j1 = j0+32, b = tid&7)
    const int j0 = tid >> 3;
    const int j1 = j0 + 32;
    const int b = tid & 7;
    const int bg = g * BG + b;
    const int jg0 = r * JS + j0;
    const int jg1 = r * JS + j1;
    const int len = lengths[bg];
    const float cp0 = g_cp[bg * HH + jg0];
    const float cp1 = g_cp[bg * HH + jg1];

    float* out0 = out + (size_t)bg * TT * HH + jg0;
    float* out1 = out + (size_t)bg * TT * HH + jg1;
    float* last0 = out + (size_t)BB * TT * HH + (size_t)bg * HH + jg0;
    float* last1 = out + (size_t)BB * TT * HH + (size_t)bg * HH + jg1;

    const unsigned fo0 = sb + FRAG_OFF + (unsigned)((j0 * FRW + b) * 4);
    const unsigned fo1 = sb + FRAG_OFF + (unsigned)((j1 * FRW + b) * 4);
    const unsigned fkh = (unsigned)(JS * FRW * 4);

    int* cnt1 = &g_cnt[1][g][0];
    int* cnt0 = &g_cnt[0][g][0];

    float xp0 = *out0;                 // prefetch xp for t=0
    float xp1 = *out1;

    __syncthreads();

    for (int t = 0; t < TT; t++) {
        const int w = (t & 1) ^ 1;

        // ---- dot via tensor cores ----
        float c[4] = {0.0f, 0.0f, 0.0f, 0.0f};
#pragma unroll
        for (int ks = 0; ks < 16; ks++) {
            const unsigned ko = (unsigned)(ks * 32);
            uint32_t ah[4], al[4], bh0, bh1, bl0, bl1;
            ldsm_x4(aHi + ko, ah[0], ah[1], ah[2], ah[3]);
            ldsm_x4(aLo + ko, al[0], al[1], al[2], al[3]);
            ldsm_x2(bHi + ko, bh0, bh1);
            ldsm_x2(bLo + ko, bl0, bl1);
            mma16816(c, ah, bh0, bh1);
            mma16816(c, ah, bl0, bl1);
            mma16816(c, al, bh0, bh1);
        }
        sts64f(fr0, c[0], c[1]);
        sts64f(fr1, c[2], c[3]);
        __syncthreads();

        // ---- owner: 2-way k reduce, tanh, publish ----
        float d0 = lds32v(fo0) + lds32v(fo0 + fkh);
        float d1 = lds32v(fo1) + lds32v(fo1 + fkh);

        const bool act = (t < len);
        float v0 = tanhf(d0 + xp0 + cp0);
        float v1 = tanhf(d1 + xp1 + cp1);

        __stcg(&g_h[w][bg][jg0], v0);
        __stcg(&g_h[w][bg][jg1], v1);

        out0[(size_t)t * HH] = act ? v0 : 0.0f;
        out1[(size_t)t * HH] = act ? v1 : 0.0f;
        if (t == len - 1) { *last0 = v0; *last1 = v1; }

        if (t == TT - 1) break;

        xp0 = out0[(size_t)(t + 1) * HH];  // prefetch under sync window
        xp1 = out1[(size_t)(t + 1) * HH];

        __syncthreads();
        if (tid == 0) {
            int* cw = w ? cnt1 : cnt0;
            asm volatile("red.release.gpu.global.add.s32 [%0], %1;"
                         :: "l"(cw), "r"(1) : "memory");
            const int target = ((t >> 1) + 1) * GR;
            int v;
            do {
                asm volatile("ld.acquire.gpu.global.s32 %0, [%1];"
                             : "=r"(v) : "l"(cw) : "memory");
            } while (v < target);
        }
        __syncthreads();

        // ---- stage: read full h (L2), split to bf16 hi/lo in SMEM ----
        {
#pragma unroll
            for (int i = 0; i < 4; i++) {
                int idx = tid + i * 256;       // 0..1023 float4 granules
                int b_i = idx >> 7;            // 0..7
                int k4 = (idx & 127) * 4;      // 0..508
                float4 v4 = __ldcg((const float4*)&g_h[w][g * BG + b_i][k4]);
                uint2 hv, lv;
                split4(v4, hv, lv);
                unsigned dst = sb + HHI_OFF + (unsigned)((b_i * WSTR + k4) * 2);
                sts64u(dst, hv.x, hv.y);
                sts64u(dst + (HLO_OFF - HHI_OFF), lv.x, lv.y);
            }
        }
        __syncthreads();
    }
}

// ---------------- launch -------------------------------------------------------

extern "C" void kernel_launch(void* const* d_in, const int* in_sizes, int n_in,
                              void* d_out, int out_size)
{
    const float* x       = (const float*)d_in[0];
    const float* cons    = (const float*)d_in[1];
    const int*   lengths = (const int*)d_in[2];
    const float* W_ih    = (const float*)d_in[3];
    const float* b_ih    = (const float*)d_in[4];
    const float* W_hh    = (const float*)d_in[5];
    const float* b_hh    = (const float*)d_in[6];
    const float* W_ch    = (const float*)d_in[7];
    const float* b_ch    = (const float*)d_in[8];
    float* out = (float*)d_out;

    // Reset group counters
    void* cnt_addr = nullptr;
    cudaGetSymbolAddress(&cnt_addr, g_cnt);
    cudaMemsetAsync(cnt_addr, 0, sizeof(int) * 2 * NG * 32);

    // Kernel order (ncu lands on the 4th kernel -> scan): cvt, xp, cp, scan
    cvt_kernel<<<4096, 256>>>(x, W_ih);

    // Phase A: xp = x @ W_ih^T + b_ih via mma.sync (bf16 split-precision)
    cudaFuncSetAttribute(xp_mma_kernel,
                         cudaFuncAttributeMaxDynamicSharedMemorySize, SMEM_X);
    xp_mma_kernel<<<dim3(8, (BB * TT) / 128), 256, SMEM_X>>>(b_ih, out);

    // Phase B: cp
    cp_kernel<<<BB, HH>>>(cons, W_ch, b_ch, b_hh);

    // Phase C: recurrence (tensor-core dot)
    cudaFuncSetAttribute(rnn_scan_kernel,
                         cudaFuncAttributeMaxDynamicSharedMemorySize, SMEM_C);
    rnn_scan_kernel<<<BB, 256, SMEM_C>>>(out, W_hh, lengths);
}